// round 3
// baseline (speedup 1.0000x reference)
#include <cuda_runtime.h>
#include <cuda_bf16.h>
#include <cstdint>

// Problem constants
#define BB 16
#define TT 64
#define SS 256
#define DD 512
#define SPLITK 4

// Scratch (device globals — no allocations allowed)
__device__ float g_wq[BB * TT * DD];            // (B,T,D)   2 MB
__device__ float g_uh[BB * SS * DD];            // (B,S,D)   8 MB
__device__ float g_concat[BB * TT * 2 * DD];    // (B,T,2D)  4 MB
__device__ float g_part[SPLITK * BB * TT * DD]; // split-K partials 8 MB

// HW tanh (sm_75+): max rel err ~2^-11, single MUFU op.
__device__ __forceinline__ float htanh(float x) {
    float y;
    asm("tanh.approx.f32 %0, %1;" : "=f"(y) : "f"(x));
    return y;
}

// ---------------------------------------------------------------------------
// GEMM core: C = A * B^T, tile BM=128 x BN=64, BK=16, 256 threads,
// thread tile 8x4, register-prefetch double buffering.
//   A: rows at A + (mbase+r)*Kld, r in [0,128)
//   B: rows at Bm + (n0+r)*Kld,   r in [0,64)
//   K range [kbeg, kend) (multiples of 16)
// ---------------------------------------------------------------------------
__device__ __forceinline__ void gemm_core(
    const float* __restrict__ A, const float* __restrict__ Bm,
    const float* __restrict__ bias, float* __restrict__ C,
    int mbase, int n0, int N, int Kld, int kbeg, int kend)
{
    __shared__ __align__(16) float As[16][132];
    __shared__ __align__(16) float Bs[16][68];

    const int tid = threadIdx.x;
    const int tx = tid & 15;   // n sub-tile (4 cols)
    const int ty = tid >> 4;   // m sub-tile (8 rows)

    const int ar0 = tid >> 2;          // A tile row 0..63
    const int ar1 = ar0 + 64;          // A tile row 64..127
    const int ak  = (tid & 3) * 4;     // k offset 0,4,8,12
    const int br  = tid >> 2;          // B tile row 0..63

    const float* Ab = A + (size_t)mbase * Kld;
    const float* Bb = Bm + (size_t)n0 * Kld;

    float4 a0v = *(const float4*)(Ab + (size_t)ar0 * Kld + kbeg + ak);
    float4 a1v = *(const float4*)(Ab + (size_t)ar1 * Kld + kbeg + ak);
    float4 bv  = *(const float4*)(Bb + (size_t)br  * Kld + kbeg + ak);

    float acc[8][4];
#pragma unroll
    for (int i = 0; i < 8; i++)
#pragma unroll
        for (int j = 0; j < 4; j++) acc[i][j] = 0.0f;

    for (int k0 = kbeg; k0 < kend; k0 += 16) {
        As[ak + 0][ar0] = a0v.x; As[ak + 1][ar0] = a0v.y;
        As[ak + 2][ar0] = a0v.z; As[ak + 3][ar0] = a0v.w;
        As[ak + 0][ar1] = a1v.x; As[ak + 1][ar1] = a1v.y;
        As[ak + 2][ar1] = a1v.z; As[ak + 3][ar1] = a1v.w;
        Bs[ak + 0][br]  = bv.x;  Bs[ak + 1][br]  = bv.y;
        Bs[ak + 2][br]  = bv.z;  Bs[ak + 3][br]  = bv.w;
        __syncthreads();

        if (k0 + 16 < kend) {
            a0v = *(const float4*)(Ab + (size_t)ar0 * Kld + k0 + 16 + ak);
            a1v = *(const float4*)(Ab + (size_t)ar1 * Kld + k0 + 16 + ak);
            bv  = *(const float4*)(Bb + (size_t)br  * Kld + k0 + 16 + ak);
        }

#pragma unroll
        for (int k = 0; k < 16; k++) {
            float4 aa0 = *(const float4*)&As[k][ty * 8];
            float4 aa1 = *(const float4*)&As[k][ty * 8 + 4];
            float4 b4  = *(const float4*)&Bs[k][tx * 4];
            float ar[8] = {aa0.x, aa0.y, aa0.z, aa0.w, aa1.x, aa1.y, aa1.z, aa1.w};
            float brr[4] = {b4.x, b4.y, b4.z, b4.w};
#pragma unroll
            for (int i = 0; i < 8; i++)
#pragma unroll
                for (int j = 0; j < 4; j++)
                    acc[i][j] = fmaf(ar[i], brr[j], acc[i][j]);
        }
        __syncthreads();
    }

    // epilogue: one float4 store per output row chunk
    float4 bb = make_float4(0.f, 0.f, 0.f, 0.f);
    if (bias) bb = *(const float4*)(bias + n0 + tx * 4);
#pragma unroll
    for (int i = 0; i < 8; i++) {
        int m = mbase + ty * 8 + i;
        float4 o;
        o.x = acc[i][0] + bb.x; o.y = acc[i][1] + bb.y;
        o.z = acc[i][2] + bb.z; o.w = acc[i][3] + bb.w;
        *(float4*)(C + (size_t)m * N + n0 + tx * 4) = o;
    }
}

// Fused wq + uh GEMM: grid.y tiles 0..7 -> wq (M=1024), 8..39 -> uh (M=4096)
__global__ __launch_bounds__(256)
void gemm_qc(const float* __restrict__ src, const float* __restrict__ mem,
             const float* __restrict__ Wq, const float* __restrict__ bq,
             const float* __restrict__ Wc,
             float* __restrict__ wq_out, float* __restrict__ uh_out) {
    int my = blockIdx.y;
    if (my < 8) {
        gemm_core(src, Wq, bq, wq_out, my * 128, blockIdx.x * 64, DD, DD, 0, DD);
    } else {
        gemm_core(mem, Wc, nullptr, uh_out, (my - 8) * 128, blockIdx.x * 64, DD, DD, 0, DD);
    }
}

// W_out GEMM, split-K=4 into partial buffers
__global__ __launch_bounds__(256)
void gemm_out(const float* __restrict__ cc, const float* __restrict__ Wout,
              float* __restrict__ part) {
    int z = blockIdx.z;
    gemm_core(cc, Wout, nullptr, part + (size_t)z * BB * TT * DD,
              blockIdx.y * 128, blockIdx.x * 64, DD, 2 * DD,
              z * (2 * DD / SPLITK), (z + 1) * (2 * DD / SPLITK));
}

// Reduce split-K partials + bias, write transposed (T,B,D)
__global__ __launch_bounds__(256)
void reduce_out(const float* __restrict__ part, const float* __restrict__ bout,
                float* __restrict__ out) {
    int i = blockIdx.x * 256 + threadIdx.x;     // float4 index, 131072 total
    int e = i * 4;
    int m = e >> 9;          // row 0..1023
    int n = e & 511;
    float4 s = make_float4(0.f, 0.f, 0.f, 0.f);
#pragma unroll
    for (int z = 0; z < SPLITK; z++) {
        float4 p = *(const float4*)(part + (size_t)z * BB * TT * DD + e);
        s.x += p.x; s.y += p.y; s.z += p.z; s.w += p.w;
    }
    float4 bb = *(const float4*)(bout + n);
    s.x += bb.x; s.y += bb.y; s.z += bb.z; s.w += bb.w;
    int b = m >> 6, t = m & 63;
    *(float4*)(out + ((size_t)(t * BB + b) << 9) + n) = s;
}

// ---------------------------------------------------------------------------
// Align + sparsemax + context + concat; 4 t's per block (uh/mem rows reused 4x)
// ---------------------------------------------------------------------------
__global__ __launch_bounds__(256)
void align4_kernel(const float* __restrict__ wq, const float* __restrict__ uh,
                   const float* __restrict__ mem, const int* __restrict__ mask,
                   const float* __restrict__ v, const float* __restrict__ src,
                   float* __restrict__ out_align, float* __restrict__ concat) {
    __shared__ float s_wq[4][DD];
    __shared__ float s_v[DD];
    __shared__ float s_z[4][SS];
    __shared__ float s_p[4][SS];
    __shared__ float s_a[SS], s_b[SS], s_r[SS];

    const int tid = threadIdx.x;
    const int b  = blockIdx.x >> 4;      // TT/4 = 16 groups per b
    const int t0 = (blockIdx.x & 15) * 4;

    for (int i = tid; i < 4 * DD; i += 256) {
        int tt = i >> 9, d = i & 511;
        s_wq[tt][d] = wq[((size_t)(b * TT + t0 + tt)) * DD + d];
    }
    s_v[tid] = v[tid];
    s_v[tid + 256] = v[tid + 256];
    __syncthreads();

    const int warp = tid >> 5, lane = tid & 31;
    for (int s = warp; s < SS; s += 8) {
        const float* uhr = uh + ((size_t)(b * SS + s)) * DD;
        float a0 = 0.f, a1 = 0.f, a2 = 0.f, a3 = 0.f;
#pragma unroll
        for (int i = 0; i < 16; i++) {
            int d = lane + i * 32;
            float u = uhr[d];
            float vv = s_v[d];
            a0 = fmaf(vv, htanh(s_wq[0][d] + u), a0);
            a1 = fmaf(vv, htanh(s_wq[1][d] + u), a1);
            a2 = fmaf(vv, htanh(s_wq[2][d] + u), a2);
            a3 = fmaf(vv, htanh(s_wq[3][d] + u), a3);
        }
#pragma unroll
        for (int off = 16; off; off >>= 1) {
            a0 += __shfl_xor_sync(0xffffffffu, a0, off);
            a1 += __shfl_xor_sync(0xffffffffu, a1, off);
            a2 += __shfl_xor_sync(0xffffffffu, a2, off);
            a3 += __shfl_xor_sync(0xffffffffu, a3, off);
        }
        if (lane == 0) {
            bool mk = mask[b * SS + s] != 0;
            s_z[0][s] = mk ? a0 : -1e9f;
            s_z[1][s] = mk ? a1 : -1e9f;
            s_z[2][s] = mk ? a2 : -1e9f;
            s_z[3][s] = mk ? a3 : -1e9f;
        }
    }
    __syncthreads();

    // sparsemax per t (sequential over 4 rows)
    for (int tt = 0; tt < 4; tt++) {
        // max reduce
        s_r[tid] = s_z[tt][tid];
        __syncthreads();
        for (int st = 128; st; st >>= 1) {
            if (tid < st) s_r[tid] = fmaxf(s_r[tid], s_r[tid + st]);
            __syncthreads();
        }
        const float zmax = s_r[0];
        const float zc = s_z[tt][tid] - zmax;
        s_a[tid] = zc;
        __syncthreads();

        // bitonic sort descending
        for (int k = 2; k <= 256; k <<= 1) {
            for (int j = k >> 1; j; j >>= 1) {
                int ixj = tid ^ j;
                if (ixj > tid) {
                    float x = s_a[tid], y = s_a[ixj];
                    bool desc = ((tid & k) == 0);
                    if ((x < y) == desc) { s_a[tid] = y; s_a[ixj] = x; }
                }
                __syncthreads();
            }
        }

        // inclusive scan
        s_b[tid] = s_a[tid];
        __syncthreads();
        for (int off = 1; off < 256; off <<= 1) {
            float val = (tid >= off) ? s_b[tid - off] : 0.0f;
            __syncthreads();
            s_b[tid] += val;
            __syncthreads();
        }

        // support size & tau
        float zcum = s_b[tid] - 1.0f;
        s_r[tid] = ((float)(tid + 1) * s_a[tid] > zcum) ? 1.0f : 0.0f;
        __syncthreads();
        for (int st = 128; st; st >>= 1) {
            if (tid < st) s_r[tid] += s_r[tid + st];
            __syncthreads();
        }
        const int supp = (int)s_r[0];
        const float tau = (s_b[supp - 1] - 1.0f) / (float)supp;

        float p = fmaxf(zc - tau, 0.0f);
        s_p[tt][tid] = p;
        out_align[((size_t)(t0 + tt) * BB + b) * SS + tid] = p;
        __syncthreads();
    }

    // context vectors (mem rows loaded once for all 4 t's) + concat
    const int d0 = tid, d1 = tid + 256;
    const float* memb = mem + (size_t)b * SS * DD;
    float c00 = 0.f, c01 = 0.f, c10 = 0.f, c11 = 0.f;
    float c20 = 0.f, c21 = 0.f, c30 = 0.f, c31 = 0.f;
    for (int s = 0; s < SS; s++) {
        float p0 = s_p[0][s], p1 = s_p[1][s], p2 = s_p[2][s], p3 = s_p[3][s];
        if (p0 + p1 + p2 + p3 != 0.0f) {
            const float* row = memb + (size_t)s * DD;
            float r0 = row[d0], r1 = row[d1];
            c00 = fmaf(p0, r0, c00); c01 = fmaf(p0, r1, c01);
            c10 = fmaf(p1, r0, c10); c11 = fmaf(p1, r1, c11);
            c20 = fmaf(p2, r0, c20); c21 = fmaf(p2, r1, c21);
            c30 = fmaf(p3, r0, c30); c31 = fmaf(p3, r1, c31);
        }
    }
    float cc0[4] = {c00, c10, c20, c30};
    float cc1[4] = {c01, c11, c21, c31};
#pragma unroll
    for (int tt = 0; tt < 4; tt++) {
        float* crow = concat + (size_t)(b * TT + t0 + tt) * (2 * DD);
        const float* srow = src + (size_t)(b * TT + t0 + tt) * DD;
        crow[d0] = cc0[tt];
        crow[d1] = cc1[tt];
        crow[DD + d0] = srow[d0];
        crow[DD + d1] = srow[d1];
    }
}

// ---------------------------------------------------------------------------
extern "C" void kernel_launch(void* const* d_in, const int* in_sizes, int n_in,
                              void* d_out, int out_size) {
    const float* source      = (const float*)d_in[0];
    const float* memory_bank = (const float*)d_in[1];
    const int*   memory_mask = (const int*)d_in[2];
    const float* W_q         = (const float*)d_in[3];
    const float* b_q         = (const float*)d_in[4];
    const float* W_c         = (const float*)d_in[5];
    const float* v           = (const float*)d_in[6];
    const float* W_out       = (const float*)d_in[7];
    const float* b_out       = (const float*)d_in[8];

    float* out       = (float*)d_out;
    float* out_attn  = out;                         // (T,B,D)
    float* out_align = out + (size_t)TT * BB * DD;  // (T,B,S)

    float *p_wq, *p_uh, *p_cc, *p_part;
    cudaGetSymbolAddress((void**)&p_wq, g_wq);
    cudaGetSymbolAddress((void**)&p_uh, g_uh);
    cudaGetSymbolAddress((void**)&p_cc, g_concat);
    cudaGetSymbolAddress((void**)&p_part, g_part);

    // fused wq & uh GEMMs: 320 blocks
    gemm_qc<<<dim3(DD / 64, 8 + 32), 256>>>(
        source, memory_bank, W_q, b_q, W_c, p_wq, p_uh);

    // align + sparsemax + context + concat: 256 blocks
    align4_kernel<<<BB * (TT / 4), 256>>>(
        p_wq, p_uh, memory_bank, memory_mask, v, source, out_align, p_cc);

    // W_out GEMM split-K: 256 blocks
    gemm_out<<<dim3(DD / 64, (BB * TT) / 128, SPLITK), 256>>>(p_cc, W_out, p_part);

    // reduce partials + bias + transpose: 512 blocks
    reduce_out<<<(BB * TT * DD) / (256 * 4), 256>>>(p_part, b_out, out_attn);
}

// round 5
// speedup vs baseline: 1.4659x; 1.4659x over previous
#include <cuda_runtime.h>
#include <cuda_bf16.h>
#include <cstdint>

// Problem constants
#define BB 16
#define TT 64
#define SS 256
#define DD 512

// Scratch (device globals — no allocations allowed)
__device__ float g_wq[BB * TT * DD];          // (B,T,D)   2 MB
__device__ float g_uh[BB * SS * DD];          // (B,S,D)   8 MB
__device__ float g_concat[BB * TT * 2 * DD];  // (B,T,2D)  4 MB

__device__ __forceinline__ float htanh(float x) {
    float y;
    asm("tanh.approx.f32 %0, %1;" : "=f"(y) : "f"(x));
    return y;
}
__device__ __forceinline__ uint32_t to_tf32(float x) {
    uint32_t r;
    asm("cvt.rna.tf32.f32 %0, %1;" : "=r"(r) : "f"(x));
    return r;
}
__device__ __forceinline__ void mma_tf32(float* d, const uint32_t* a, const uint32_t* b) {
    asm volatile(
        "mma.sync.aligned.m16n8k8.row.col.f32.tf32.tf32.f32 "
        "{%0,%1,%2,%3}, {%4,%5,%6,%7}, {%8,%9}, {%0,%1,%2,%3};"
        : "+f"(d[0]), "+f"(d[1]), "+f"(d[2]), "+f"(d[3])
        : "r"(a[0]), "r"(a[1]), "r"(a[2]), "r"(a[3]), "r"(b[0]), "r"(b[1]));
}

// ---------------------------------------------------------------------------
// tf32 mma.sync GEMM: C = A(M x Kld) * B(N x Kld)^T (+bias)
// CTA tile 128 x BN, BK=32, 256 threads (warps: 4 along M, 2 along N).
// Warp tile 32 x (BN/2). smem rows padded to 36 floats (conflict-free frags).
// OUT_MODE 0: C[m*Nld+n]; OUT_MODE 1: m=b*TT+t -> C[(t*BB+b)*Nld+n]
// ---------------------------------------------------------------------------
template <int BN, int NC, int OUT_MODE>
__device__ void mma_gemm_dev(const float* __restrict__ A, const float* __restrict__ Bm,
                             const float* __restrict__ bias, float* __restrict__ C,
                             int mbase, int n0, int Nld, int Kld) {
    constexpr int WN = BN / 2;        // warp n-tile
    constexpr int NB = WN / 8;        // n8 fragments per warp
    constexpr int ASZ = 128 * 36;     // floats per A buffer
    constexpr int BSZ = BN * 36;

    extern __shared__ __align__(16) uint32_t sm[];
    uint32_t* SA[2] = {sm, sm + ASZ};
    uint32_t* SB[2] = {sm + 2 * ASZ, sm + 2 * ASZ + BSZ};

    const int tid = threadIdx.x;
    const int wid = tid >> 5, lane = tid & 31;
    const int wm = wid & 3;           // warp m index (0..3)
    const int wn = wid >> 2;          // warp n index (0..1)
    const int gid = lane >> 2;        // groupID
    const int tig = lane & 3;         // threadID_in_group

    const float* Ab = A + (size_t)mbase * Kld;
    const float* Bb = Bm + (size_t)n0 * Kld;

    float d[2][NB][4];
#pragma unroll
    for (int f = 0; f < 2; f++)
#pragma unroll
        for (int nb = 0; nb < NB; nb++)
#pragma unroll
            for (int c = 0; c < 4; c++) d[f][nb][c] = 0.0f;

    // ---- chunk loader: global -> cvt.rna -> smem (uint4 stores) ----
    auto load_chunk = [&](int buf, int k0) {
#pragma unroll
        for (int it = 0; it < 4; it++) {
            int idx = tid + it * 256;
            int r = idx >> 3, j = idx & 7;
            float4 v = *(const float4*)(Ab + (size_t)r * Kld + k0 + j * 4);
            uint4 u = make_uint4(to_tf32(v.x), to_tf32(v.y), to_tf32(v.z), to_tf32(v.w));
            *(uint4*)(SA[buf] + r * 36 + j * 4) = u;
        }
#pragma unroll
        for (int it = 0; it < BN / 32; it++) {
            int idx = tid + it * 256;
            int r = idx >> 3, j = idx & 7;
            float4 v = *(const float4*)(Bb + (size_t)r * Kld + k0 + j * 4);
            uint4 u = make_uint4(to_tf32(v.x), to_tf32(v.y), to_tf32(v.z), to_tf32(v.w));
            *(uint4*)(SB[buf] + r * 36 + j * 4) = u;
        }
    };

    load_chunk(0, 0);
    __syncthreads();

    for (int i = 0; i < NC; i++) {
        const int p = i & 1;
        if (i + 1 < NC) load_chunk(p ^ 1, (i + 1) * 32);

        const uint32_t* sa = SA[p];
        const uint32_t* sb = SB[p];
#pragma unroll
        for (int s = 0; s < 4; s++) {
            uint32_t a[2][4];
#pragma unroll
            for (int f = 0; f < 2; f++) {
                int r0 = (wm * 32 + f * 16 + gid) * 36 + s * 8 + tig;
                int r1 = r0 + 8 * 36;
                a[f][0] = sa[r0];
                a[f][1] = sa[r1];
                a[f][2] = sa[r0 + 4];
                a[f][3] = sa[r1 + 4];
            }
            uint32_t b[NB][2];
#pragma unroll
            for (int nb = 0; nb < NB; nb++) {
                int rb = (wn * WN + nb * 8 + gid) * 36 + s * 8 + tig;
                b[nb][0] = sb[rb];
                b[nb][1] = sb[rb + 4];
            }
#pragma unroll
            for (int f = 0; f < 2; f++)
#pragma unroll
                for (int nb = 0; nb < NB; nb++)
                    mma_tf32(d[f][nb], a[f], b[nb]);
        }
        __syncthreads();
    }

    // ---- epilogue ----
#pragma unroll
    for (int f = 0; f < 2; f++) {
        int m0 = mbase + wm * 32 + f * 16 + gid;
        int m1 = m0 + 8;
        float* row0;
        float* row1;
        if (OUT_MODE == 0) {
            row0 = C + (size_t)m0 * Nld;
            row1 = C + (size_t)m1 * Nld;
        } else {
            row0 = C + (size_t)((m0 & 63) * BB + (m0 >> 6)) * Nld;
            row1 = C + (size_t)((m1 & 63) * BB + (m1 >> 6)) * Nld;
        }
#pragma unroll
        for (int nb = 0; nb < NB; nb++) {
            int cn = n0 + wn * WN + nb * 8 + 2 * tig;
            float2 bb = make_float2(0.f, 0.f);
            if (bias) bb = *(const float2*)(bias + cn);
            float2 o0 = make_float2(d[f][nb][0] + bb.x, d[f][nb][1] + bb.y);
            float2 o1 = make_float2(d[f][nb][2] + bb.x, d[f][nb][3] + bb.y);
            *(float2*)(row0 + cn) = o0;
            *(float2*)(row1 + cn) = o1;
        }
    }
}

// Fused wq + uh GEMM: grid.y 0..7 -> wq (M=1024), 8..39 -> uh (M=4096); grid.x=4
__global__ __launch_bounds__(256)
void gqc_mma(const float* __restrict__ src, const float* __restrict__ mem,
             const float* __restrict__ Wq, const float* __restrict__ bq,
             const float* __restrict__ Wc,
             float* __restrict__ wq, float* __restrict__ uh) {
    int my = blockIdx.y;
    if (my < 8)
        mma_gemm_dev<128, 16, 0>(src, Wq, bq, wq, my * 128, blockIdx.x * 128, DD, DD);
    else
        mma_gemm_dev<128, 16, 0>(mem, Wc, nullptr, uh, (my - 8) * 128, blockIdx.x * 128, DD, DD);
}

// Output GEMM: concat(1024x1024) @ W_out^T(512x1024) + bias, (T,B,D) transpose fused
__global__ __launch_bounds__(256)
void gout_mma(const float* __restrict__ cc, const float* __restrict__ Wout,
              const float* __restrict__ bout, float* __restrict__ out) {
    mma_gemm_dev<64, 32, 1>(cc, Wout, bout, out, blockIdx.y * 128, blockIdx.x * 64,
                            DD, 2 * DD);
}

// ---------------------------------------------------------------------------
// Align + sparsemax + context + concat; 4 t's per block; masked s-rows skipped
// ---------------------------------------------------------------------------
__global__ __launch_bounds__(256)
void align4_kernel(const float* __restrict__ wq, const float* __restrict__ uh,
                   const float* __restrict__ mem, const int* __restrict__ mask,
                   const float* __restrict__ v, const float* __restrict__ src,
                   float* __restrict__ out_align, float* __restrict__ concat) {
    __shared__ float s_wq[4][DD];
    __shared__ float s_v[DD];
    __shared__ float s_z[4][SS];
    __shared__ float s_p[4][SS];
    __shared__ float s_a[SS], s_b[SS], s_r[SS];
    __shared__ int s_mk[SS];

    const int tid = threadIdx.x;
    const int b  = blockIdx.x >> 4;
    const int t0 = (blockIdx.x & 15) * 4;

    for (int i = tid; i < 4 * DD; i += 256) {
        int tt = i >> 9, d = i & 511;
        s_wq[tt][d] = wq[((size_t)(b * TT + t0 + tt)) * DD + d];
    }
    s_v[tid] = v[tid];
    s_v[tid + 256] = v[tid + 256];
    s_mk[tid] = mask[b * SS + tid];
    __syncthreads();

    const int warp = tid >> 5, lane = tid & 31;
    for (int s = warp; s < SS; s += 8) {
        if (!s_mk[s]) {
            if (lane == 0) {
                s_z[0][s] = -1e9f; s_z[1][s] = -1e9f;
                s_z[2][s] = -1e9f; s_z[3][s] = -1e9f;
            }
            continue;
        }
        const float* uhr = uh + ((size_t)(b * SS + s)) * DD;
        float a0 = 0.f, a1 = 0.f, a2 = 0.f, a3 = 0.f;
#pragma unroll
        for (int i = 0; i < 16; i++) {
            int d = lane + i * 32;
            float u = uhr[d];
            float vv = s_v[d];
            a0 = fmaf(vv, htanh(s_wq[0][d] + u), a0);
            a1 = fmaf(vv, htanh(s_wq[1][d] + u), a1);
            a2 = fmaf(vv, htanh(s_wq[2][d] + u), a2);
            a3 = fmaf(vv, htanh(s_wq[3][d] + u), a3);
        }
#pragma unroll
        for (int off = 16; off; off >>= 1) {
            a0 += __shfl_xor_sync(0xffffffffu, a0, off);
            a1 += __shfl_xor_sync(0xffffffffu, a1, off);
            a2 += __shfl_xor_sync(0xffffffffu, a2, off);
            a3 += __shfl_xor_sync(0xffffffffu, a3, off);
        }
        if (lane == 0) {
            s_z[0][s] = a0; s_z[1][s] = a1; s_z[2][s] = a2; s_z[3][s] = a3;
        }
    }
    __syncthreads();

    for (int tt = 0; tt < 4; tt++) {
        // max reduce
        s_r[tid] = s_z[tt][tid];
        __syncthreads();
        for (int st = 128; st; st >>= 1) {
            if (tid < st) s_r[tid] = fmaxf(s_r[tid], s_r[tid + st]);
            __syncthreads();
        }
        const float zmax = s_r[0];
        const float zc = s_z[tt][tid] - zmax;
        s_a[tid] = zc;
        __syncthreads();

        // bitonic sort descending
        for (int k = 2; k <= 256; k <<= 1) {
            for (int j = k >> 1; j; j >>= 1) {
                int ixj = tid ^ j;
                if (ixj > tid) {
                    float x = s_a[tid], y = s_a[ixj];
                    bool desc = ((tid & k) == 0);
                    if ((x < y) == desc) { s_a[tid] = y; s_a[ixj] = x; }
                }
                __syncthreads();
            }
        }

        // inclusive scan
        s_b[tid] = s_a[tid];
        __syncthreads();
        for (int off = 1; off < 256; off <<= 1) {
            float val = (tid >= off) ? s_b[tid - off] : 0.0f;
            __syncthreads();
            s_b[tid] += val;
            __syncthreads();
        }

        // support size & tau
        float zcum = s_b[tid] - 1.0f;
        s_r[tid] = ((float)(tid + 1) * s_a[tid] > zcum) ? 1.0f : 0.0f;
        __syncthreads();
        for (int st = 128; st; st >>= 1) {
            if (tid < st) s_r[tid] += s_r[tid + st];
            __syncthreads();
        }
        const int supp = (int)s_r[0];
        const float tau = (s_b[supp - 1] - 1.0f) / (float)supp;

        float p = fmaxf(zc - tau, 0.0f);
        s_p[tt][tid] = p;
        out_align[((size_t)(t0 + tt) * BB + b) * SS + tid] = p;
        __syncthreads();
    }

    // context vectors + concat
    const int d0 = tid, d1 = tid + 256;
    const float* memb = mem + (size_t)b * SS * DD;
    float c00 = 0.f, c01 = 0.f, c10 = 0.f, c11 = 0.f;
    float c20 = 0.f, c21 = 0.f, c30 = 0.f, c31 = 0.f;
    for (int s = 0; s < SS; s++) {
        float p0 = s_p[0][s], p1 = s_p[1][s], p2 = s_p[2][s], p3 = s_p[3][s];
        if (p0 + p1 + p2 + p3 != 0.0f) {
            const float* row = memb + (size_t)s * DD;
            float r0 = row[d0], r1 = row[d1];
            c00 = fmaf(p0, r0, c00); c01 = fmaf(p0, r1, c01);
            c10 = fmaf(p1, r0, c10); c11 = fmaf(p1, r1, c11);
            c20 = fmaf(p2, r0, c20); c21 = fmaf(p2, r1, c21);
            c30 = fmaf(p3, r0, c30); c31 = fmaf(p3, r1, c31);
        }
    }
    float cc0[4] = {c00, c10, c20, c30};
    float cc1[4] = {c01, c11, c21, c31};
#pragma unroll
    for (int tt = 0; tt < 4; tt++) {
        float* crow = concat + (size_t)(b * TT + t0 + tt) * (2 * DD);
        const float* srow = src + (size_t)(b * TT + t0 + tt) * DD;
        crow[d0] = cc0[tt];
        crow[d1] = cc1[tt];
        crow[DD + d0] = srow[d0];
        crow[DD + d1] = srow[d1];
    }
}

// ---------------------------------------------------------------------------
extern "C" void kernel_launch(void* const* d_in, const int* in_sizes, int n_in,
                              void* d_out, int out_size) {
    const float* source      = (const float*)d_in[0];
    const float* memory_bank = (const float*)d_in[1];
    const int*   memory_mask = (const int*)d_in[2];
    const float* W_q         = (const float*)d_in[3];
    const float* b_q         = (const float*)d_in[4];
    const float* W_c         = (const float*)d_in[5];
    const float* v           = (const float*)d_in[6];
    const float* W_out       = (const float*)d_in[7];
    const float* b_out       = (const float*)d_in[8];

    float* out       = (float*)d_out;
    float* out_attn  = out;                         // (T,B,D)
    float* out_align = out + (size_t)TT * BB * DD;  // (T,B,S)

    float *p_wq, *p_uh, *p_cc;
    cudaGetSymbolAddress((void**)&p_wq, g_wq);
    cudaGetSymbolAddress((void**)&p_uh, g_uh);
    cudaGetSymbolAddress((void**)&p_cc, g_concat);

    // dynamic smem: 2*(A 128*36 + B BN*36) uint32
    const int smem_qc  = 2 * (128 * 36 + 128 * 36) * 4;  // 73728
    const int smem_out = 2 * (128 * 36 + 64 * 36) * 4;   // 55296
    cudaFuncSetAttribute(gqc_mma, cudaFuncAttributeMaxDynamicSharedMemorySize, smem_qc);
    cudaFuncSetAttribute(gout_mma, cudaFuncAttributeMaxDynamicSharedMemorySize, smem_out);

    // wq & uh (tf32 mma.sync): 160 CTAs
    gqc_mma<<<dim3(4, 40), 256, smem_qc>>>(
        source, memory_bank, W_q, b_q, W_c, p_wq, p_uh);

    // align + sparsemax + context + concat: 256 CTAs
    align4_kernel<<<BB * (TT / 4), 256>>>(
        p_wq, p_uh, memory_bank, memory_mask, v, source, out_align, p_cc);

    // attn_h = concat @ W_out^T + b_out -> (T,B,D): 64 CTAs
    gout_mma<<<dim3(8, 8), 256, smem_out>>>(p_cc, W_out, b_out, out_attn);
}

// round 6
// speedup vs baseline: 1.7100x; 1.1665x over previous
#include <cuda_runtime.h>
#include <cuda_bf16.h>
#include <cstdint>

// Problem constants
#define BB 16
#define TT 64
#define SS 256
#define DD 512

// Scratch (device globals — no allocations allowed)
__device__ float g_wq[BB * TT * DD];          // (B,T,D)   2 MB
__device__ float g_uh[BB * SS * DD];          // (B,S,D)   8 MB
__device__ float g_concat[BB * TT * 2 * DD];  // (B,T,2D)  4 MB

__device__ __forceinline__ float htanh(float x) {
    float y;
    asm("tanh.approx.f32 %0, %1;" : "=f"(y) : "f"(x));
    return y;
}
__device__ __forceinline__ uint32_t to_tf32(float x) {
    uint32_t r;
    asm("cvt.rna.tf32.f32 %0, %1;" : "=r"(r) : "f"(x));
    return r;
}
__device__ __forceinline__ void mma_tf32(float* d, const uint32_t* a, const uint32_t* b) {
    asm volatile(
        "mma.sync.aligned.m16n8k8.row.col.f32.tf32.tf32.f32 "
        "{%0,%1,%2,%3}, {%4,%5,%6,%7}, {%8,%9}, {%0,%1,%2,%3};"
        : "+f"(d[0]), "+f"(d[1]), "+f"(d[2]), "+f"(d[3])
        : "r"(a[0]), "r"(a[1]), "r"(a[2]), "r"(a[3]), "r"(b[0]), "r"(b[1]));
}

// ---------------------------------------------------------------------------
// tf32 mma.sync GEMM: C = A(M x Kld) * B(N x Kld)^T (+bias)
// CTA tile BM x BN, BK=32, 256 threads. Warp grid: (BM/32) x (8/(BM/32)).
// Warp m-tile fixed 32; warp n-tile WN = BN/WARPS_N, NB = WN/8 fragments.
// smem rows padded to 36 floats (conflict-free fragment LDS).
// OUT_MODE 0: C[m*Nld+n]; OUT_MODE 1: m=b*TT+t -> C[(t*BB+b)*Nld+n]
// ---------------------------------------------------------------------------
template <int BM, int BN, int NC, int OUT_MODE>
__device__ void mma_gemm_dev(const float* __restrict__ A, const float* __restrict__ Bm,
                             const float* __restrict__ bias, float* __restrict__ C,
                             int mbase, int n0, int Nld, int Kld) {
    constexpr int WARPS_M = BM / 32;
    constexpr int WARPS_N = 8 / WARPS_M;
    constexpr int WN = BN / WARPS_N;
    constexpr int NB = WN / 8;
    constexpr int ASZ = BM * 36;
    constexpr int BSZ = BN * 36;

    extern __shared__ __align__(16) uint32_t sm[];
    uint32_t* SA[2] = {sm, sm + ASZ};
    uint32_t* SB[2] = {sm + 2 * ASZ, sm + 2 * ASZ + BSZ};

    const int tid = threadIdx.x;
    const int wid = tid >> 5, lane = tid & 31;
    const int wm = wid % WARPS_M;
    const int wn = wid / WARPS_M;
    const int gid = lane >> 2;        // groupID
    const int tig = lane & 3;         // threadID_in_group

    const float* Ab = A + (size_t)mbase * Kld;
    const float* Bb = Bm + (size_t)n0 * Kld;

    float d[2][NB][4];
#pragma unroll
    for (int f = 0; f < 2; f++)
#pragma unroll
        for (int nb = 0; nb < NB; nb++)
#pragma unroll
            for (int c = 0; c < 4; c++) d[f][nb][c] = 0.0f;

    auto load_chunk = [&](int buf, int k0) {
#pragma unroll
        for (int it = 0; it < BM / 32; it++) {
            int idx = tid + it * 256;
            int r = idx >> 3, j = idx & 7;
            float4 v = *(const float4*)(Ab + (size_t)r * Kld + k0 + j * 4);
            uint4 u = make_uint4(to_tf32(v.x), to_tf32(v.y), to_tf32(v.z), to_tf32(v.w));
            *(uint4*)(SA[buf] + r * 36 + j * 4) = u;
        }
#pragma unroll
        for (int it = 0; it < BN / 32; it++) {
            int idx = tid + it * 256;
            int r = idx >> 3, j = idx & 7;
            float4 v = *(const float4*)(Bb + (size_t)r * Kld + k0 + j * 4);
            uint4 u = make_uint4(to_tf32(v.x), to_tf32(v.y), to_tf32(v.z), to_tf32(v.w));
            *(uint4*)(SB[buf] + r * 36 + j * 4) = u;
        }
    };

    load_chunk(0, 0);
    __syncthreads();

    for (int i = 0; i < NC; i++) {
        const int p = i & 1;
        if (i + 1 < NC) load_chunk(p ^ 1, (i + 1) * 32);

        const uint32_t* sa = SA[p];
        const uint32_t* sb = SB[p];
#pragma unroll
        for (int s = 0; s < 4; s++) {
            uint32_t a[2][4];
#pragma unroll
            for (int f = 0; f < 2; f++) {
                int r0 = (wm * 32 + f * 16 + gid) * 36 + s * 8 + tig;
                int r1 = r0 + 8 * 36;
                a[f][0] = sa[r0];
                a[f][1] = sa[r1];
                a[f][2] = sa[r0 + 4];
                a[f][3] = sa[r1 + 4];
            }
            uint32_t b[NB][2];
#pragma unroll
            for (int nb = 0; nb < NB; nb++) {
                int rb = (wn * WN + nb * 8 + gid) * 36 + s * 8 + tig;
                b[nb][0] = sb[rb];
                b[nb][1] = sb[rb + 4];
            }
#pragma unroll
            for (int f = 0; f < 2; f++)
#pragma unroll
                for (int nb = 0; nb < NB; nb++)
                    mma_tf32(d[f][nb], a[f], b[nb]);
        }
        __syncthreads();
    }

    // ---- epilogue ----
#pragma unroll
    for (int f = 0; f < 2; f++) {
        int m0 = mbase + wm * 32 + f * 16 + gid;
        int m1 = m0 + 8;
        float* row0;
        float* row1;
        if (OUT_MODE == 0) {
            row0 = C + (size_t)m0 * Nld;
            row1 = C + (size_t)m1 * Nld;
        } else {
            row0 = C + (size_t)((m0 & 63) * BB + (m0 >> 6)) * Nld;
            row1 = C + (size_t)((m1 & 63) * BB + (m1 >> 6)) * Nld;
        }
#pragma unroll
        for (int nb = 0; nb < NB; nb++) {
            int cn = n0 + wn * WN + nb * 8 + 2 * tig;
            float2 bb = make_float2(0.f, 0.f);
            if (bias) bb = *(const float2*)(bias + cn);
            float2 o0 = make_float2(d[f][nb][0] + bb.x, d[f][nb][1] + bb.y);
            float2 o1 = make_float2(d[f][nb][2] + bb.x, d[f][nb][3] + bb.y);
            *(float2*)(row0 + cn) = o0;
            *(float2*)(row1 + cn) = o1;
        }
    }
}

// Fused wq + uh GEMM: grid.y 0..7 -> wq (M=1024), 8..39 -> uh (M=4096); grid.x=8
__global__ __launch_bounds__(256)
void gqc_mma(const float* __restrict__ src, const float* __restrict__ mem,
             const float* __restrict__ Wq, const float* __restrict__ bq,
             const float* __restrict__ Wc,
             float* __restrict__ wq, float* __restrict__ uh) {
    int my = blockIdx.y;
    if (my < 8)
        mma_gemm_dev<128, 64, 16, 0>(src, Wq, bq, wq, my * 128, blockIdx.x * 64, DD, DD);
    else
        mma_gemm_dev<128, 64, 16, 0>(mem, Wc, nullptr, uh, (my - 8) * 128, blockIdx.x * 64, DD, DD);
}

// Output GEMM: concat(1024x1024) @ W_out^T(512x1024) + bias, (T,B,D) transpose fused
__global__ __launch_bounds__(256)
void gout_mma(const float* __restrict__ cc, const float* __restrict__ Wout,
              const float* __restrict__ bout, float* __restrict__ out) {
    mma_gemm_dev<64, 64, 32, 1>(cc, Wout, bout, out, blockIdx.y * 64, blockIdx.x * 64,
                                DD, 2 * DD);
}

// ---------------------------------------------------------------------------
// Align + sparsemax (Michelot threshold iteration, exact) + context + concat.
// 4 t's per block; masked s-rows skipped (halves MUFU tanh work).
// ---------------------------------------------------------------------------
__global__ __launch_bounds__(256)
void align4_kernel(const float* __restrict__ wq, const float* __restrict__ uh,
                   const float* __restrict__ mem, const int* __restrict__ mask,
                   const float* __restrict__ v, const float* __restrict__ src,
                   float* __restrict__ out_align, float* __restrict__ concat) {
    __shared__ float s_wq[4][DD];
    __shared__ float s_v[DD];
    __shared__ float s_z[4][SS];
    __shared__ float s_p[4][SS];
    __shared__ int s_mk[SS];
    __shared__ float s_sum[8], s_cnt[8];
    __shared__ float s_tau;
    __shared__ int s_c;

    const int tid = threadIdx.x;
    const int b  = blockIdx.x >> 4;
    const int t0 = (blockIdx.x & 15) * 4;

    for (int i = tid; i < 4 * DD; i += 256) {
        int tt = i >> 9, d = i & 511;
        s_wq[tt][d] = wq[((size_t)(b * TT + t0 + tt)) * DD + d];
    }
    s_v[tid] = v[tid];
    s_v[tid + 256] = v[tid + 256];
    s_mk[tid] = mask[b * SS + tid];
    __syncthreads();

    const int warp = tid >> 5, lane = tid & 31;
    for (int s = warp; s < SS; s += 8) {
        if (!s_mk[s]) {
            if (lane == 0) {
                s_z[0][s] = -1e9f; s_z[1][s] = -1e9f;
                s_z[2][s] = -1e9f; s_z[3][s] = -1e9f;
            }
            continue;
        }
        const float* uhr = uh + ((size_t)(b * SS + s)) * DD;
        float a0 = 0.f, a1 = 0.f, a2 = 0.f, a3 = 0.f;
#pragma unroll
        for (int i = 0; i < 16; i++) {
            int d = lane + i * 32;
            float u = uhr[d];
            float vv = s_v[d];
            a0 = fmaf(vv, htanh(s_wq[0][d] + u), a0);
            a1 = fmaf(vv, htanh(s_wq[1][d] + u), a1);
            a2 = fmaf(vv, htanh(s_wq[2][d] + u), a2);
            a3 = fmaf(vv, htanh(s_wq[3][d] + u), a3);
        }
#pragma unroll
        for (int off = 16; off; off >>= 1) {
            a0 += __shfl_xor_sync(0xffffffffu, a0, off);
            a1 += __shfl_xor_sync(0xffffffffu, a1, off);
            a2 += __shfl_xor_sync(0xffffffffu, a2, off);
            a3 += __shfl_xor_sync(0xffffffffu, a3, off);
        }
        if (lane == 0) {
            s_z[0][s] = a0; s_z[1][s] = a1; s_z[2][s] = a2; s_z[3][s] = a3;
        }
    }
    __syncthreads();

    // ---- sparsemax via Michelot: tau = (sum_{z>tau} z - 1)/count, active set
    // shrinks monotonically, terminates exactly when count is stable. ----
    for (int tt = 0; tt < 4; tt++) {
        const float z = s_z[tt][tid];
        bool act = true;
        int prev_cnt = -1;
        float tau = 0.0f;
        for (int it = 0; it < 256; it++) {
            float sv = act ? z : 0.0f;
            float cv = act ? 1.0f : 0.0f;
#pragma unroll
            for (int off = 16; off; off >>= 1) {
                sv += __shfl_xor_sync(0xffffffffu, sv, off);
                cv += __shfl_xor_sync(0xffffffffu, cv, off);
            }
            if (lane == 0) { s_sum[warp] = sv; s_cnt[warp] = cv; }
            __syncthreads();
            if (tid == 0) {
                float ts = 0.f, tc = 0.f;
#pragma unroll
                for (int w = 0; w < 8; w++) { ts += s_sum[w]; tc += s_cnt[w]; }
                s_tau = (ts - 1.0f) / tc;
                s_c = (int)tc;
            }
            __syncthreads();
            int c = s_c;
            if (c == prev_cnt) break;   // active set stable -> tau (prev) final
            tau = s_tau;
            act = z > tau;
            prev_cnt = c;
            __syncthreads();
        }
        float p = fmaxf(z - tau, 0.0f);
        s_p[tt][tid] = p;
        out_align[((size_t)(t0 + tt) * BB + b) * SS + tid] = p;
        __syncthreads();
    }

    // ---- context vectors (mem rows shared by 4 t's) + concat ----
    const int d0 = tid, d1 = tid + 256;
    const float* memb = mem + (size_t)b * SS * DD;
    float c00 = 0.f, c01 = 0.f, c10 = 0.f, c11 = 0.f;
    float c20 = 0.f, c21 = 0.f, c30 = 0.f, c31 = 0.f;
    for (int s = 0; s < SS; s++) {
        float p0 = s_p[0][s], p1 = s_p[1][s], p2 = s_p[2][s], p3 = s_p[3][s];
        if (p0 + p1 + p2 + p3 != 0.0f) {
            const float* row = memb + (size_t)s * DD;
            float r0 = row[d0], r1 = row[d1];
            c00 = fmaf(p0, r0, c00); c01 = fmaf(p0, r1, c01);
            c10 = fmaf(p1, r0, c10); c11 = fmaf(p1, r1, c11);
            c20 = fmaf(p2, r0, c20); c21 = fmaf(p2, r1, c21);
            c30 = fmaf(p3, r0, c30); c31 = fmaf(p3, r1, c31);
        }
    }
    float cc0[4] = {c00, c10, c20, c30};
    float cc1[4] = {c01, c11, c21, c31};
#pragma unroll
    for (int tt = 0; tt < 4; tt++) {
        float* crow = concat + (size_t)(b * TT + t0 + tt) * (2 * DD);
        const float* srow = src + (size_t)(b * TT + t0 + tt) * DD;
        crow[d0] = cc0[tt];
        crow[d1] = cc1[tt];
        crow[DD + d0] = srow[d0];
        crow[DD + d1] = srow[d1];
    }
}

// ---------------------------------------------------------------------------
extern "C" void kernel_launch(void* const* d_in, const int* in_sizes, int n_in,
                              void* d_out, int out_size) {
    const float* source      = (const float*)d_in[0];
    const float* memory_bank = (const float*)d_in[1];
    const int*   memory_mask = (const int*)d_in[2];
    const float* W_q         = (const float*)d_in[3];
    const float* b_q         = (const float*)d_in[4];
    const float* W_c         = (const float*)d_in[5];
    const float* v           = (const float*)d_in[6];
    const float* W_out       = (const float*)d_in[7];
    const float* b_out       = (const float*)d_in[8];

    float* out       = (float*)d_out;
    float* out_attn  = out;                         // (T,B,D)
    float* out_align = out + (size_t)TT * BB * DD;  // (T,B,S)

    float *p_wq, *p_uh, *p_cc;
    cudaGetSymbolAddress((void**)&p_wq, g_wq);
    cudaGetSymbolAddress((void**)&p_uh, g_uh);
    cudaGetSymbolAddress((void**)&p_cc, g_concat);

    // dynamic smem: 2*(BM*36 + BN*36) uint32
    const int smem_qc  = 2 * (128 * 36 + 64 * 36) * 4;  // 55296
    const int smem_out = 2 * (64 * 36 + 64 * 36) * 4;   // 36864
    cudaFuncSetAttribute(gqc_mma, cudaFuncAttributeMaxDynamicSharedMemorySize, smem_qc);
    cudaFuncSetAttribute(gout_mma, cudaFuncAttributeMaxDynamicSharedMemorySize, smem_out);

    // wq & uh (tf32 mma.sync): 320 CTAs
    gqc_mma<<<dim3(8, 40), 256, smem_qc>>>(
        source, memory_bank, W_q, b_q, W_c, p_wq, p_uh);

    // align + sparsemax + context + concat: 256 CTAs
    align4_kernel<<<BB * (TT / 4), 256>>>(
        p_wq, p_uh, memory_bank, memory_mask, v, source, out_align, p_cc);

    // attn_h = concat @ W_out^T + b_out -> (T,B,D): 128 CTAs
    gout_mma<<<dim3(8, 16), 256, smem_out>>>(p_cc, W_out, b_out, out_attn);
}

// round 7
// speedup vs baseline: 1.8005x; 1.0529x over previous
#include <cuda_runtime.h>
#include <cuda_bf16.h>
#include <cstdint>

// Problem constants
#define BB 16
#define TT 64
#define SS 256
#define DD 512

// Scratch (device globals — no allocations allowed)
__device__ float g_wq[BB * TT * DD];          // (B,T,D)   2 MB
__device__ float g_uh[BB * SS * DD];          // (B,S,D)   8 MB
__device__ float g_concat[BB * TT * 2 * DD];  // (B,T,2D)  4 MB

__device__ __forceinline__ float htanh(float x) {
    float y;
    asm("tanh.approx.f32 %0, %1;" : "=f"(y) : "f"(x));
    return y;
}
__device__ __forceinline__ uint32_t to_tf32(float x) {
    uint32_t r;
    asm("cvt.rna.tf32.f32 %0, %1;" : "=r"(r) : "f"(x));
    return r;
}
__device__ __forceinline__ void mma_tf32(float* d, const uint32_t* a, const uint32_t* b) {
    asm volatile(
        "mma.sync.aligned.m16n8k8.row.col.f32.tf32.tf32.f32 "
        "{%0,%1,%2,%3}, {%4,%5,%6,%7}, {%8,%9}, {%0,%1,%2,%3};"
        : "+f"(d[0]), "+f"(d[1]), "+f"(d[2]), "+f"(d[3])
        : "r"(a[0]), "r"(a[1]), "r"(a[2]), "r"(a[3]), "r"(b[0]), "r"(b[1]));
}

// ---------------------------------------------------------------------------
// tf32 mma.sync GEMM: C = A(M x Kld) * B(N x Kld)^T (+bias)
// CTA tile BM x BN, BK=32, 256 threads. Warp grid (BM/32) x (8/(BM/32)).
// Fragment registers double-buffered across the 4 s-steps (LDS for s+1
// overlaps mma of s); fragment addresses hoisted to loop-invariant pointers.
// smem rows padded to 36 floats (conflict-free fragment LDS).
// OUT_MODE 0: C[m*Nld+n]; OUT_MODE 1: m=b*TT+t -> C[(t*BB+b)*Nld+n]
// ---------------------------------------------------------------------------
template <int BM, int BN, int NC, int OUT_MODE>
__device__ void mma_gemm_dev(const float* __restrict__ A, const float* __restrict__ Bm,
                             const float* __restrict__ bias, float* __restrict__ C,
                             int mbase, int n0, int Nld, int Kld) {
    constexpr int WARPS_M = BM / 32;
    constexpr int WARPS_N = 8 / WARPS_M;
    constexpr int WN = BN / WARPS_N;
    constexpr int NB = WN / 8;
    constexpr int ASZ = BM * 36;
    constexpr int BSZ = BN * 36;

    extern __shared__ __align__(16) uint32_t sm[];
    uint32_t* SA[2] = {sm, sm + ASZ};
    uint32_t* SB[2] = {sm + 2 * ASZ, sm + 2 * ASZ + BSZ};

    const int tid = threadIdx.x;
    const int wid = tid >> 5, lane = tid & 31;
    const int wm = wid % WARPS_M;
    const int wn = wid / WARPS_M;
    const int gid = lane >> 2;        // groupID
    const int tig = lane & 3;         // threadID_in_group

    const float* Ab = A + (size_t)mbase * Kld;
    const float* Bb = Bm + (size_t)n0 * Kld;

    float d[2][NB][4];
#pragma unroll
    for (int f = 0; f < 2; f++)
#pragma unroll
        for (int nb = 0; nb < NB; nb++)
#pragma unroll
            for (int c = 0; c < 4; c++) d[f][nb][c] = 0.0f;

    auto load_chunk = [&](int buf, int k0) {
#pragma unroll
        for (int it = 0; it < BM / 32; it++) {
            int idx = tid + it * 256;
            int r = idx >> 3, j = idx & 7;
            float4 v = *(const float4*)(Ab + (size_t)r * Kld + k0 + j * 4);
            uint4 u = make_uint4(to_tf32(v.x), to_tf32(v.y), to_tf32(v.z), to_tf32(v.w));
            *(uint4*)(SA[buf] + r * 36 + j * 4) = u;
        }
#pragma unroll
        for (int it = 0; it < BN / 32; it++) {
            int idx = tid + it * 256;
            int r = idx >> 3, j = idx & 7;
            float4 v = *(const float4*)(Bb + (size_t)r * Kld + k0 + j * 4);
            uint4 u = make_uint4(to_tf32(v.x), to_tf32(v.y), to_tf32(v.z), to_tf32(v.w));
            *(uint4*)(SB[buf] + r * 36 + j * 4) = u;
        }
    };

    const int pa_off = (wm * 32 + gid) * 36 + tig;   // invariant fragment bases
    const int pb_off = (wn * WN + gid) * 36 + tig;

    load_chunk(0, 0);
    __syncthreads();

    for (int i = 0; i < NC; i++) {
        const int p = i & 1;
        if (i + 1 < NC) load_chunk(p ^ 1, (i + 1) * 32);

        const uint32_t* pa = SA[p] + pa_off;
        const uint32_t* pb = SB[p] + pb_off;

        uint32_t af[2][2][4];     // [s-parity][f][frag]
        uint32_t bf[2][NB][2];    // [s-parity][nb][frag]

        // prime s = 0
#pragma unroll
        for (int f = 0; f < 2; f++) {
            const uint32_t* q = pa + f * (16 * 36);
            af[0][f][0] = q[0];
            af[0][f][1] = q[8 * 36];
            af[0][f][2] = q[4];
            af[0][f][3] = q[8 * 36 + 4];
        }
#pragma unroll
        for (int nb = 0; nb < NB; nb++) {
            const uint32_t* q = pb + nb * (8 * 36);
            bf[0][nb][0] = q[0];
            bf[0][nb][1] = q[4];
        }

#pragma unroll
        for (int s = 0; s < 4; s++) {
            const int cur = s & 1, nxt = cur ^ 1;
            if (s < 3) {
                const int ko = (s + 1) * 8;
#pragma unroll
                for (int f = 0; f < 2; f++) {
                    const uint32_t* q = pa + f * (16 * 36) + ko;
                    af[nxt][f][0] = q[0];
                    af[nxt][f][1] = q[8 * 36];
                    af[nxt][f][2] = q[4];
                    af[nxt][f][3] = q[8 * 36 + 4];
                }
#pragma unroll
                for (int nb = 0; nb < NB; nb++) {
                    const uint32_t* q = pb + nb * (8 * 36) + ko;
                    bf[nxt][nb][0] = q[0];
                    bf[nxt][nb][1] = q[4];
                }
            }
#pragma unroll
            for (int f = 0; f < 2; f++)
#pragma unroll
                for (int nb = 0; nb < NB; nb++)
                    mma_tf32(d[f][nb], af[cur][f], bf[cur][nb]);
        }
        __syncthreads();
    }

    // ---- epilogue ----
#pragma unroll
    for (int f = 0; f < 2; f++) {
        int m0 = mbase + wm * 32 + f * 16 + gid;
        int m1 = m0 + 8;
        float* row0;
        float* row1;
        if (OUT_MODE == 0) {
            row0 = C + (size_t)m0 * Nld;
            row1 = C + (size_t)m1 * Nld;
        } else {
            row0 = C + (size_t)((m0 & 63) * BB + (m0 >> 6)) * Nld;
            row1 = C + (size_t)((m1 & 63) * BB + (m1 >> 6)) * Nld;
        }
#pragma unroll
        for (int nb = 0; nb < NB; nb++) {
            int cn = n0 + wn * WN + nb * 8 + 2 * tig;
            float2 bb = make_float2(0.f, 0.f);
            if (bias) bb = *(const float2*)(bias + cn);
            float2 o0 = make_float2(d[f][nb][0] + bb.x, d[f][nb][1] + bb.y);
            float2 o1 = make_float2(d[f][nb][2] + bb.x, d[f][nb][3] + bb.y);
            *(float2*)(row0 + cn) = o0;
            *(float2*)(row1 + cn) = o1;
        }
    }
}

// Fused wq + uh GEMM: grid.y 0..7 -> wq (M=1024), 8..39 -> uh (M=4096); grid.x=8
__global__ __launch_bounds__(256, 2)
void gqc_mma(const float* __restrict__ src, const float* __restrict__ mem,
             const float* __restrict__ Wq, const float* __restrict__ bq,
             const float* __restrict__ Wc,
             float* __restrict__ wq, float* __restrict__ uh) {
    int my = blockIdx.y;
    if (my < 8)
        mma_gemm_dev<128, 64, 16, 0>(src, Wq, bq, wq, my * 128, blockIdx.x * 64, DD, DD);
    else
        mma_gemm_dev<128, 64, 16, 0>(mem, Wc, nullptr, uh, (my - 8) * 128, blockIdx.x * 64, DD, DD);
}

// Output GEMM: concat(1024x1024) @ W_out^T(512x1024) + bias, (T,B,D) transpose fused
__global__ __launch_bounds__(256, 2)
void gout_mma(const float* __restrict__ cc, const float* __restrict__ Wout,
              const float* __restrict__ bout, float* __restrict__ out) {
    mma_gemm_dev<64, 64, 32, 1>(cc, Wout, bout, out, blockIdx.y * 64, blockIdx.x * 64,
                                DD, 2 * DD);
}

// ---------------------------------------------------------------------------
// Align + sparsemax (Michelot threshold iteration, exact) + context + concat.
// 4 t's per block; masked s-rows skipped (halves MUFU tanh work).
// ---------------------------------------------------------------------------
__global__ __launch_bounds__(256)
void align4_kernel(const float* __restrict__ wq, const float* __restrict__ uh,
                   const float* __restrict__ mem, const int* __restrict__ mask,
                   const float* __restrict__ v, const float* __restrict__ src,
                   float* __restrict__ out_align, float* __restrict__ concat) {
    __shared__ float s_wq[4][DD];
    __shared__ float s_v[DD];
    __shared__ float s_z[4][SS];
    __shared__ float s_p[4][SS];
    __shared__ int s_mk[SS];
    __shared__ float s_sum[8], s_cnt[8];
    __shared__ float s_tau;
    __shared__ int s_c;

    const int tid = threadIdx.x;
    const int b  = blockIdx.x >> 4;
    const int t0 = (blockIdx.x & 15) * 4;

    for (int i = tid; i < 4 * DD; i += 256) {
        int tt = i >> 9, d = i & 511;
        s_wq[tt][d] = wq[((size_t)(b * TT + t0 + tt)) * DD + d];
    }
    s_v[tid] = v[tid];
    s_v[tid + 256] = v[tid + 256];
    s_mk[tid] = mask[b * SS + tid];
    __syncthreads();

    const int warp = tid >> 5, lane = tid & 31;
    for (int s = warp; s < SS; s += 8) {
        if (!s_mk[s]) {
            if (lane == 0) {
                s_z[0][s] = -1e9f; s_z[1][s] = -1e9f;
                s_z[2][s] = -1e9f; s_z[3][s] = -1e9f;
            }
            continue;
        }
        const float* uhr = uh + ((size_t)(b * SS + s)) * DD;
        float a0 = 0.f, a1 = 0.f, a2 = 0.f, a3 = 0.f;
#pragma unroll
        for (int i = 0; i < 16; i++) {
            int d = lane + i * 32;
            float u = uhr[d];
            float vv = s_v[d];
            a0 = fmaf(vv, htanh(s_wq[0][d] + u), a0);
            a1 = fmaf(vv, htanh(s_wq[1][d] + u), a1);
            a2 = fmaf(vv, htanh(s_wq[2][d] + u), a2);
            a3 = fmaf(vv, htanh(s_wq[3][d] + u), a3);
        }
#pragma unroll
        for (int off = 16; off; off >>= 1) {
            a0 += __shfl_xor_sync(0xffffffffu, a0, off);
            a1 += __shfl_xor_sync(0xffffffffu, a1, off);
            a2 += __shfl_xor_sync(0xffffffffu, a2, off);
            a3 += __shfl_xor_sync(0xffffffffu, a3, off);
        }
        if (lane == 0) {
            s_z[0][s] = a0; s_z[1][s] = a1; s_z[2][s] = a2; s_z[3][s] = a3;
        }
    }
    __syncthreads();

    // ---- sparsemax via Michelot: tau = (sum_{z>tau} z - 1)/count; active set
    // shrinks monotonically; exact when count stabilizes. ----
    for (int tt = 0; tt < 4; tt++) {
        const float z = s_z[tt][tid];
        bool act = true;
        int prev_cnt = -1;
        float tau = 0.0f;
        for (int it = 0; it < 256; it++) {
            float sv = act ? z : 0.0f;
            float cv = act ? 1.0f : 0.0f;
#pragma unroll
            for (int off = 16; off; off >>= 1) {
                sv += __shfl_xor_sync(0xffffffffu, sv, off);
                cv += __shfl_xor_sync(0xffffffffu, cv, off);
            }
            if (lane == 0) { s_sum[warp] = sv; s_cnt[warp] = cv; }
            __syncthreads();
            if (tid == 0) {
                float ts = 0.f, tc = 0.f;
#pragma unroll
                for (int w = 0; w < 8; w++) { ts += s_sum[w]; tc += s_cnt[w]; }
                s_tau = (ts - 1.0f) / tc;
                s_c = (int)tc;
            }
            __syncthreads();
            int c = s_c;
            if (c == prev_cnt) break;
            tau = s_tau;
            act = z > tau;
            prev_cnt = c;
            __syncthreads();
        }
        float p = fmaxf(z - tau, 0.0f);
        s_p[tt][tid] = p;
        out_align[((size_t)(t0 + tt) * BB + b) * SS + tid] = p;
        __syncthreads();
    }

    // ---- context vectors (mem rows shared by 4 t's) + concat ----
    const int d0 = tid, d1 = tid + 256;
    const float* memb = mem + (size_t)b * SS * DD;
    float c00 = 0.f, c01 = 0.f, c10 = 0.f, c11 = 0.f;
    float c20 = 0.f, c21 = 0.f, c30 = 0.f, c31 = 0.f;
    for (int s = 0; s < SS; s++) {
        float p0 = s_p[0][s], p1 = s_p[1][s], p2 = s_p[2][s], p3 = s_p[3][s];
        if (p0 + p1 + p2 + p3 != 0.0f) {
            const float* row = memb + (size_t)s * DD;
            float r0 = row[d0], r1 = row[d1];
            c00 = fmaf(p0, r0, c00); c01 = fmaf(p0, r1, c01);
            c10 = fmaf(p1, r0, c10); c11 = fmaf(p1, r1, c11);
            c20 = fmaf(p2, r0, c20); c21 = fmaf(p2, r1, c21);
            c30 = fmaf(p3, r0, c30); c31 = fmaf(p3, r1, c31);
        }
    }
    float cc0[4] = {c00, c10, c20, c30};
    float cc1[4] = {c01, c11, c21, c31};
#pragma unroll
    for (int tt = 0; tt < 4; tt++) {
        float* crow = concat + (size_t)(b * TT + t0 + tt) * (2 * DD);
        const float* srow = src + (size_t)(b * TT + t0 + tt) * DD;
        crow[d0] = cc0[tt];
        crow[d1] = cc1[tt];
        crow[DD + d0] = srow[d0];
        crow[DD + d1] = srow[d1];
    }
}

// ---------------------------------------------------------------------------
extern "C" void kernel_launch(void* const* d_in, const int* in_sizes, int n_in,
                              void* d_out, int out_size) {
    const float* source      = (const float*)d_in[0];
    const float* memory_bank = (const float*)d_in[1];
    const int*   memory_mask = (const int*)d_in[2];
    const float* W_q         = (const float*)d_in[3];
    const float* b_q         = (const float*)d_in[4];
    const float* W_c         = (const float*)d_in[5];
    const float* v           = (const float*)d_in[6];
    const float* W_out       = (const float*)d_in[7];
    const float* b_out       = (const float*)d_in[8];

    float* out       = (float*)d_out;
    float* out_attn  = out;                         // (T,B,D)
    float* out_align = out + (size_t)TT * BB * DD;  // (T,B,S)

    float *p_wq, *p_uh, *p_cc;
    cudaGetSymbolAddress((void**)&p_wq, g_wq);
    cudaGetSymbolAddress((void**)&p_uh, g_uh);
    cudaGetSymbolAddress((void**)&p_cc, g_concat);

    // dynamic smem: 2*(BM*36 + BN*36) uint32
    const int smem_qc  = 2 * (128 * 36 + 64 * 36) * 4;  // 55296
    const int smem_out = 2 * (64 * 36 + 64 * 36) * 4;   // 36864
    cudaFuncSetAttribute(gqc_mma, cudaFuncAttributeMaxDynamicSharedMemorySize, smem_qc);
    cudaFuncSetAttribute(gout_mma, cudaFuncAttributeMaxDynamicSharedMemorySize, smem_out);

    // wq & uh (tf32 mma.sync): 320 CTAs
    gqc_mma<<<dim3(8, 40), 256, smem_qc>>>(
        source, memory_bank, W_q, b_q, W_c, p_wq, p_uh);

    // align + sparsemax + context + concat: 256 CTAs
    align4_kernel<<<BB * (TT / 4), 256>>>(
        p_wq, p_uh, memory_bank, memory_mask, v, source, out_align, p_cc);

    // attn_h = concat @ W_out^T + b_out -> (T,B,D): 128 CTAs
    gout_mma<<<dim3(8, 16), 256, smem_out>>>(p_cc, W_out, b_out, out_attn);
}

// round 8
// speedup vs baseline: 2.2028x; 1.2234x over previous
#include <cuda_runtime.h>
#include <cuda_bf16.h>
#include <cstdint>

// Problem constants
#define BB 16
#define TT 64
#define SS 256
#define DD 512

// Scratch (device globals — no allocations allowed)
__device__ float g_wq[BB * TT * DD];          // (B,T,D)   2 MB
__device__ float g_uh[BB * SS * DD];          // (B,S,D)   8 MB
__device__ float g_concat[BB * TT * 2 * DD];  // (B,T,2D)  4 MB

__device__ __forceinline__ float htanh(float x) {
    float y;
    asm("tanh.approx.f32 %0, %1;" : "=f"(y) : "f"(x));
    return y;
}
__device__ __forceinline__ uint32_t to_tf32(uint32_t fp32_bits) {
    uint32_t r;
    asm("cvt.rna.tf32.f32 %0, %1;" : "=r"(r) : "f"(__uint_as_float(fp32_bits)));
    return r;
}
__device__ __forceinline__ void mma_tf32(float* d, const uint32_t* a, const uint32_t* b) {
    asm volatile(
        "mma.sync.aligned.m16n8k8.row.col.f32.tf32.tf32.f32 "
        "{%0,%1,%2,%3}, {%4,%5,%6,%7}, {%8,%9}, {%0,%1,%2,%3};"
        : "+f"(d[0]), "+f"(d[1]), "+f"(d[2]), "+f"(d[3])
        : "r"(a[0]), "r"(a[1]), "r"(a[2]), "r"(a[3]), "r"(b[0]), "r"(b[1]));
}
__device__ __forceinline__ uint32_t cvta_sh(const void* p) {
    uint32_t a;
    asm("{ .reg .u64 t; cvta.to.shared.u64 t, %1; cvt.u32.u64 %0, t; }"
        : "=r"(a) : "l"(p));
    return a;
}
__device__ __forceinline__ void cp16(uint32_t dst, const void* src) {
    asm volatile("cp.async.cg.shared.global [%0], [%1], 16;"
                 :: "r"(dst), "l"(src) : "memory");
}
#define CP_COMMIT() asm volatile("cp.async.commit_group;" ::: "memory")
#define CP_WAIT2()  asm volatile("cp.async.wait_group 2;" ::: "memory")

// ---------------------------------------------------------------------------
// tf32 mma.sync GEMM: C = A(M x Kld) * B(N x Kld)^T (+bias)
// CTA tile BM x BN, BK=32, 256 threads, warp grid (BM/32) x (8/(BM/32)).
// 4-stage cp.async pipeline (raw fp32 in smem; cvt.rna at fragment consume).
// One commit_group per chunk (empty commits in the tail), wait_group 2 +
// one __syncthreads per iteration. smem rows padded to 36 floats.
// OUT_MODE 0: C[m*Nld+n]; OUT_MODE 1: m=b*TT+t -> C[(t*BB+b)*Nld+n]
// ---------------------------------------------------------------------------
template <int BM, int BN, int NC, int OUT_MODE>
__device__ void mma_gemm_dev(const float* __restrict__ A, const float* __restrict__ Bm,
                             const float* __restrict__ bias, float* __restrict__ C,
                             int mbase, int n0, int Nld, int Kld) {
    constexpr int WARPS_M = BM / 32;
    constexpr int WARPS_N = 8 / WARPS_M;
    constexpr int WN = BN / WARPS_N;
    constexpr int NB = WN / 8;
    constexpr int CH = (BM + BN) * 36;    // uint32 per stage
    constexpr int STG = 4;

    extern __shared__ __align__(16) uint32_t sm[];
    const uint32_t sm_sh = cvta_sh(sm);

    const int tid = threadIdx.x;
    const int wid = tid >> 5, lane = tid & 31;
    const int wm = wid % WARPS_M;
    const int wn = wid / WARPS_M;
    const int gid = lane >> 2;
    const int tig = lane & 3;

    const float* Ab = A + (size_t)mbase * Kld;
    const float* Bb = Bm + (size_t)n0 * Kld;

    float d[2][NB][4];
#pragma unroll
    for (int f = 0; f < 2; f++)
#pragma unroll
        for (int nb = 0; nb < NB; nb++)
#pragma unroll
            for (int c = 0; c < 4; c++) d[f][nb][c] = 0.0f;

    const int lr = tid >> 3;            // loader row
    const int lj = tid & 7;             // loader 16B-col
    auto cp_chunk = [&](int st, int k0) {
        uint32_t abase = sm_sh + (uint32_t)st * CH * 4;
#pragma unroll
        for (int it = 0; it < BM / 32; it++) {
            int r = lr + it * 32;
            cp16(abase + (uint32_t)(r * 36 + lj * 4) * 4,
                 Ab + (size_t)r * Kld + k0 + lj * 4);
        }
        uint32_t bbase = abase + BM * 36 * 4;
#pragma unroll
        for (int it = 0; it < BN / 32; it++) {
            int r = lr + it * 32;
            cp16(bbase + (uint32_t)(r * 36 + lj * 4) * 4,
                 Bb + (size_t)r * Kld + k0 + lj * 4);
        }
    };

    // prologue: stages 0..2
#pragma unroll
    for (int i = 0; i < STG - 1; i++) {
        if (i < NC) cp_chunk(i, i * 32);
        CP_COMMIT();
    }

    const int pa_off = (wm * 32 + gid) * 36 + tig;
    const int pb_off = (wn * WN + gid) * 36 + tig;

    for (int i = 0; i < NC; i++) {
        CP_WAIT2();
        __syncthreads();

        const int st = i & (STG - 1);
        const uint32_t* sa = sm + st * CH + pa_off;
        const uint32_t* sb = sm + st * CH + BM * 36 + pb_off;

#pragma unroll
        for (int s = 0; s < 4; s++) {
            const int ko = s * 8;
            uint32_t a[2][4];
#pragma unroll
            for (int f = 0; f < 2; f++) {
                const uint32_t* q = sa + f * (16 * 36) + ko;
                a[f][0] = to_tf32(q[0]);
                a[f][1] = to_tf32(q[8 * 36]);
                a[f][2] = to_tf32(q[4]);
                a[f][3] = to_tf32(q[8 * 36 + 4]);
            }
            uint32_t b[NB][2];
#pragma unroll
            for (int nb = 0; nb < NB; nb++) {
                const uint32_t* q = sb + nb * (8 * 36) + ko;
                b[nb][0] = to_tf32(q[0]);
                b[nb][1] = to_tf32(q[4]);
            }
#pragma unroll
            for (int f = 0; f < 2; f++)
#pragma unroll
                for (int nb = 0; nb < NB; nb++)
                    mma_tf32(d[f][nb], a[f], b[nb]);
        }

        const int nx = i + STG - 1;
        if (nx < NC) cp_chunk(nx & (STG - 1), nx * 32);
        CP_COMMIT();
    }

    // ---- epilogue ----
#pragma unroll
    for (int f = 0; f < 2; f++) {
        int m0 = mbase + wm * 32 + f * 16 + gid;
        int m1 = m0 + 8;
        float* row0;
        float* row1;
        if (OUT_MODE == 0) {
            row0 = C + (size_t)m0 * Nld;
            row1 = C + (size_t)m1 * Nld;
        } else {
            row0 = C + (size_t)((m0 & 63) * BB + (m0 >> 6)) * Nld;
            row1 = C + (size_t)((m1 & 63) * BB + (m1 >> 6)) * Nld;
        }
#pragma unroll
        for (int nb = 0; nb < NB; nb++) {
            int cn = n0 + wn * WN + nb * 8 + 2 * tig;
            float2 bb = make_float2(0.f, 0.f);
            if (bias) bb = *(const float2*)(bias + cn);
            float2 o0 = make_float2(d[f][nb][0] + bb.x, d[f][nb][1] + bb.y);
            float2 o1 = make_float2(d[f][nb][2] + bb.x, d[f][nb][3] + bb.y);
            *(float2*)(row0 + cn) = o0;
            *(float2*)(row1 + cn) = o1;
        }
    }
}

// Fused wq + uh GEMM: grid.y 0..7 -> wq (M=1024), 8..39 -> uh (M=4096); grid.x=8
__global__ __launch_bounds__(256, 2)
void gqc_mma(const float* __restrict__ src, const float* __restrict__ mem,
             const float* __restrict__ Wq, const float* __restrict__ bq,
             const float* __restrict__ Wc,
             float* __restrict__ wq, float* __restrict__ uh) {
    int my = blockIdx.y;
    if (my < 8)
        mma_gemm_dev<128, 64, 16, 0>(src, Wq, bq, wq, my * 128, blockIdx.x * 64, DD, DD);
    else
        mma_gemm_dev<128, 64, 16, 0>(mem, Wc, nullptr, uh, (my - 8) * 128, blockIdx.x * 64, DD, DD);
}

// Output GEMM: concat(1024x1024) @ W_out^T(512x1024) + bias, (T,B,D) transpose fused
__global__ __launch_bounds__(256, 2)
void gout_mma(const float* __restrict__ cc, const float* __restrict__ Wout,
              const float* __restrict__ bout, float* __restrict__ out) {
    mma_gemm_dev<64, 64, 32, 1>(cc, Wout, bout, out, blockIdx.y * 64, blockIdx.x * 64,
                                DD, 2 * DD);
}

// ---------------------------------------------------------------------------
// Align + sparsemax (Michelot threshold iteration, exact) + context + concat.
// 4 t's per block; masked s-rows skipped (halves MUFU tanh work).
// ---------------------------------------------------------------------------
__global__ __launch_bounds__(256)
void align4_kernel(const float* __restrict__ wq, const float* __restrict__ uh,
                   const float* __restrict__ mem, const int* __restrict__ mask,
                   const float* __restrict__ v, const float* __restrict__ src,
                   float* __restrict__ out_align, float* __restrict__ concat) {
    __shared__ float s_wq[4][DD];
    __shared__ float s_v[DD];
    __shared__ float s_z[4][SS];
    __shared__ float s_p[4][SS];
    __shared__ int s_mk[SS];
    __shared__ float s_sum[8], s_cnt[8];
    __shared__ float s_tau;
    __shared__ int s_c;

    const int tid = threadIdx.x;
    const int b  = blockIdx.x >> 4;
    const int t0 = (blockIdx.x & 15) * 4;

    for (int i = tid; i < 4 * DD; i += 256) {
        int tt = i >> 9, d = i & 511;
        s_wq[tt][d] = wq[((size_t)(b * TT + t0 + tt)) * DD + d];
    }
    s_v[tid] = v[tid];
    s_v[tid + 256] = v[tid + 256];
    s_mk[tid] = mask[b * SS + tid];
    __syncthreads();

    const int warp = tid >> 5, lane = tid & 31;
    for (int s = warp; s < SS; s += 8) {
        if (!s_mk[s]) {
            if (lane == 0) {
                s_z[0][s] = -1e9f; s_z[1][s] = -1e9f;
                s_z[2][s] = -1e9f; s_z[3][s] = -1e9f;
            }
            continue;
        }
        const float* uhr = uh + ((size_t)(b * SS + s)) * DD;
        float a0 = 0.f, a1 = 0.f, a2 = 0.f, a3 = 0.f;
#pragma unroll
        for (int i = 0; i < 16; i++) {
            int d = lane + i * 32;
            float u = uhr[d];
            float vv = s_v[d];
            a0 = fmaf(vv, htanh(s_wq[0][d] + u), a0);
            a1 = fmaf(vv, htanh(s_wq[1][d] + u), a1);
            a2 = fmaf(vv, htanh(s_wq[2][d] + u), a2);
            a3 = fmaf(vv, htanh(s_wq[3][d] + u), a3);
        }
#pragma unroll
        for (int off = 16; off; off >>= 1) {
            a0 += __shfl_xor_sync(0xffffffffu, a0, off);
            a1 += __shfl_xor_sync(0xffffffffu, a1, off);
            a2 += __shfl_xor_sync(0xffffffffu, a2, off);
            a3 += __shfl_xor_sync(0xffffffffu, a3, off);
        }
        if (lane == 0) {
            s_z[0][s] = a0; s_z[1][s] = a1; s_z[2][s] = a2; s_z[3][s] = a3;
        }
    }
    __syncthreads();

    // sparsemax via Michelot: tau = (sum_{z>tau} z - 1)/count; exact on stability
    for (int tt = 0; tt < 4; tt++) {
        const float z = s_z[tt][tid];
        bool act = true;
        int prev_cnt = -1;
        float tau = 0.0f;
        for (int it = 0; it < 256; it++) {
            float sv = act ? z : 0.0f;
            float cv = act ? 1.0f : 0.0f;
#pragma unroll
            for (int off = 16; off; off >>= 1) {
                sv += __shfl_xor_sync(0xffffffffu, sv, off);
                cv += __shfl_xor_sync(0xffffffffu, cv, off);
            }
            if (lane == 0) { s_sum[warp] = sv; s_cnt[warp] = cv; }
            __syncthreads();
            if (tid == 0) {
                float ts = 0.f, tc = 0.f;
#pragma unroll
                for (int w = 0; w < 8; w++) { ts += s_sum[w]; tc += s_cnt[w]; }
                s_tau = (ts - 1.0f) / tc;
                s_c = (int)tc;
            }
            __syncthreads();
            int c = s_c;
            if (c == prev_cnt) break;
            tau = s_tau;
            act = z > tau;
            prev_cnt = c;
            __syncthreads();
        }
        float p = fmaxf(z - tau, 0.0f);
        s_p[tt][tid] = p;
        out_align[((size_t)(t0 + tt) * BB + b) * SS + tid] = p;
        __syncthreads();
    }

    // context vectors (mem rows shared by 4 t's) + concat
    const int d0 = tid, d1 = tid + 256;
    const float* memb = mem + (size_t)b * SS * DD;
    float c00 = 0.f, c01 = 0.f, c10 = 0.f, c11 = 0.f;
    float c20 = 0.f, c21 = 0.f, c30 = 0.f, c31 = 0.f;
    for (int s = 0; s < SS; s++) {
        float p0 = s_p[0][s], p1 = s_p[1][s], p2 = s_p[2][s], p3 = s_p[3][s];
        if (p0 + p1 + p2 + p3 != 0.0f) {
            const float* row = memb + (size_t)s * DD;
            float r0 = row[d0], r1 = row[d1];
            c00 = fmaf(p0, r0, c00); c01 = fmaf(p0, r1, c01);
            c10 = fmaf(p1, r0, c10); c11 = fmaf(p1, r1, c11);
            c20 = fmaf(p2, r0, c20); c21 = fmaf(p2, r1, c21);
            c30 = fmaf(p3, r0, c30); c31 = fmaf(p3, r1, c31);
        }
    }
    float cc0[4] = {c00, c10, c20, c30};
    float cc1[4] = {c01, c11, c21, c31};
#pragma unroll
    for (int tt = 0; tt < 4; tt++) {
        float* crow = concat + (size_t)(b * TT + t0 + tt) * (2 * DD);
        const float* srow = src + (size_t)(b * TT + t0 + tt) * DD;
        crow[d0] = cc0[tt];
        crow[d1] = cc1[tt];
        crow[DD + d0] = srow[d0];
        crow[DD + d1] = srow[d1];
    }
}

// ---------------------------------------------------------------------------
extern "C" void kernel_launch(void* const* d_in, const int* in_sizes, int n_in,
                              void* d_out, int out_size) {
    const float* source      = (const float*)d_in[0];
    const float* memory_bank = (const float*)d_in[1];
    const int*   memory_mask = (const int*)d_in[2];
    const float* W_q         = (const float*)d_in[3];
    const float* b_q         = (const float*)d_in[4];
    const float* W_c         = (const float*)d_in[5];
    const float* v           = (const float*)d_in[6];
    const float* W_out       = (const float*)d_in[7];
    const float* b_out       = (const float*)d_in[8];

    float* out       = (float*)d_out;
    float* out_attn  = out;                         // (T,B,D)
    float* out_align = out + (size_t)TT * BB * DD;  // (T,B,S)

    float *p_wq, *p_uh, *p_cc;
    cudaGetSymbolAddress((void**)&p_wq, g_wq);
    cudaGetSymbolAddress((void**)&p_uh, g_uh);
    cudaGetSymbolAddress((void**)&p_cc, g_concat);

    // dynamic smem: 4 stages * (BM+BN)*36 uint32
    const int smem_qc  = 4 * (128 + 64) * 36 * 4;  // 110592
    const int smem_out = 4 * (64 + 64) * 36 * 4;   // 73728
    cudaFuncSetAttribute(gqc_mma, cudaFuncAttributeMaxDynamicSharedMemorySize, smem_qc);
    cudaFuncSetAttribute(gout_mma, cudaFuncAttributeMaxDynamicSharedMemorySize, smem_out);

    // wq & uh (tf32 mma.sync + cp.async): 320 CTAs
    gqc_mma<<<dim3(8, 40), 256, smem_qc>>>(
        source, memory_bank, W_q, b_q, W_c, p_wq, p_uh);

    // align + sparsemax + context + concat: 256 CTAs
    align4_kernel<<<BB * (TT / 4), 256>>>(
        p_wq, p_uh, memory_bank, memory_mask, v, source, out_align, p_cc);

    // attn_h = concat @ W_out^T + b_out -> (T,B,D): 128 CTAs
    gout_mma<<<dim3(8, 16), 256, smem_out>>>(p_cc, W_out, b_out, out_attn);
}

// round 9
// speedup vs baseline: 2.2953x; 1.0420x over previous
#include <cuda_runtime.h>
#include <cuda_bf16.h>
#include <cstdint>

// Problem constants
#define BB 16
#define TT 64
#define SS 256
#define DD 512

// Scratch (device globals — no allocations allowed)
__device__ float g_wq[BB * TT * DD];          // (B,T,D)   2 MB
__device__ float g_uh[BB * SS * DD];          // (B,S,D)   8 MB
__device__ float g_concat[BB * TT * 2 * DD];  // (B,T,2D)  4 MB (tf32-rounded)
// tf32-pre-rounded copies of GEMM inputs
__device__ float g_rsrc[BB * TT * DD];        // 2 MB
__device__ float g_rmem[BB * SS * DD];        // 8 MB
__device__ float g_rwq[DD * DD];              // 1 MB
__device__ float g_rwc[DD * DD];              // 1 MB
__device__ float g_rwout[DD * 2 * DD];        // 2 MB

__device__ __forceinline__ float htanh(float x) {
    float y;
    asm("tanh.approx.f32 %0, %1;" : "=f"(y) : "f"(x));
    return y;
}
__device__ __forceinline__ uint32_t to_tf32(float x) {
    uint32_t r;
    asm("cvt.rna.tf32.f32 %0, %1;" : "=r"(r) : "f"(x));
    return r;
}
__device__ __forceinline__ void mma_tf32(float* d, const uint32_t* a, const uint32_t* b) {
    asm volatile(
        "mma.sync.aligned.m16n8k8.row.col.f32.tf32.tf32.f32 "
        "{%0,%1,%2,%3}, {%4,%5,%6,%7}, {%8,%9}, {%0,%1,%2,%3};"
        : "+f"(d[0]), "+f"(d[1]), "+f"(d[2]), "+f"(d[3])
        : "r"(a[0]), "r"(a[1]), "r"(a[2]), "r"(a[3]), "r"(b[0]), "r"(b[1]));
}
__device__ __forceinline__ uint32_t cvta_sh(const void* p) {
    uint32_t a;
    asm("{ .reg .u64 t; cvta.to.shared.u64 t, %1; cvt.u32.u64 %0, t; }"
        : "=r"(a) : "l"(p));
    return a;
}
__device__ __forceinline__ void cp16(uint32_t dst, const void* src) {
    asm volatile("cp.async.cg.shared.global [%0], [%1], 16;"
                 :: "r"(dst), "l"(src) : "memory");
}
#define CP_COMMIT() asm volatile("cp.async.commit_group;" ::: "memory")
#define CP_WAIT2()  asm volatile("cp.async.wait_group 2;" ::: "memory")
#define BAR64(id)   asm volatile("bar.sync %0, 64;" :: "r"(id) : "memory")

// ---------------------------------------------------------------------------
// Pre-round pass: cvt.rna.tf32 all GEMM inputs once (segment per blockIdx.y).
// ---------------------------------------------------------------------------
__global__ __launch_bounds__(256)
void round_kernel(const float* __restrict__ src, const float* __restrict__ mem,
                  const float* __restrict__ Wq, const float* __restrict__ Wc,
                  const float* __restrict__ Wout,
                  float* __restrict__ rsrc, float* __restrict__ rmem,
                  float* __restrict__ rwq, float* __restrict__ rwc,
                  float* __restrict__ rwout) {
    const int seg = blockIdx.y;
    const float* in;
    float* outp;
    int n4;
    switch (seg) {
        case 0: in = src;  outp = rsrc;  n4 = BB * TT * DD / 4; break;
        case 1: in = mem;  outp = rmem;  n4 = BB * SS * DD / 4; break;
        case 2: in = Wq;   outp = rwq;   n4 = DD * DD / 4; break;
        case 3: in = Wc;   outp = rwc;   n4 = DD * DD / 4; break;
        default: in = Wout; outp = rwout; n4 = DD * 2 * DD / 4; break;
    }
    int i = blockIdx.x * 256 + threadIdx.x;
    if (i >= n4) return;
    float4 v = *(const float4*)(in + i * 4);
    float4 o;
    o.x = __uint_as_float(to_tf32(v.x));
    o.y = __uint_as_float(to_tf32(v.y));
    o.z = __uint_as_float(to_tf32(v.z));
    o.w = __uint_as_float(to_tf32(v.w));
    *(float4*)(outp + i * 4) = o;
}

// ---------------------------------------------------------------------------
// tf32 mma.sync GEMM on pre-rounded inputs: C = A(M x Kld) * B(N x Kld)^T.
// CTA tile BM x BN, BK=32, 256 threads, 4-stage cp.async pipeline.
// No cvt in the mainloop — operands already on the tf32 grid.
// OUT_MODE 0: C[m*Nld+n]; OUT_MODE 1: m=b*TT+t -> C[(t*BB+b)*Nld+n]
// ---------------------------------------------------------------------------
template <int BM, int BN, int NC, int OUT_MODE>
__device__ void mma_gemm_dev(const float* __restrict__ A, const float* __restrict__ Bm,
                             const float* __restrict__ bias, float* __restrict__ C,
                             int mbase, int n0, int Nld, int Kld) {
    constexpr int WARPS_M = BM / 32;
    constexpr int WARPS_N = 8 / WARPS_M;
    constexpr int WN = BN / WARPS_N;
    constexpr int NB = WN / 8;
    constexpr int CH = (BM + BN) * 36;
    constexpr int STG = 4;

    extern __shared__ __align__(16) uint32_t sm[];
    const uint32_t sm_sh = cvta_sh(sm);

    const int tid = threadIdx.x;
    const int wid = tid >> 5, lane = tid & 31;
    const int wm = wid % WARPS_M;
    const int wn = wid / WARPS_M;
    const int gid = lane >> 2;
    const int tig = lane & 3;

    const float* Ab = A + (size_t)mbase * Kld;
    const float* Bb = Bm + (size_t)n0 * Kld;

    float d[2][NB][4];
#pragma unroll
    for (int f = 0; f < 2; f++)
#pragma unroll
        for (int nb = 0; nb < NB; nb++)
#pragma unroll
            for (int c = 0; c < 4; c++) d[f][nb][c] = 0.0f;

    const int lr = tid >> 3;
    const int lj = tid & 7;
    auto cp_chunk = [&](int st, int k0) {
        uint32_t abase = sm_sh + (uint32_t)st * CH * 4;
#pragma unroll
        for (int it = 0; it < BM / 32; it++) {
            int r = lr + it * 32;
            cp16(abase + (uint32_t)(r * 36 + lj * 4) * 4,
                 Ab + (size_t)r * Kld + k0 + lj * 4);
        }
        uint32_t bbase = abase + BM * 36 * 4;
#pragma unroll
        for (int it = 0; it < BN / 32; it++) {
            int r = lr + it * 32;
            cp16(bbase + (uint32_t)(r * 36 + lj * 4) * 4,
                 Bb + (size_t)r * Kld + k0 + lj * 4);
        }
    };

#pragma unroll
    for (int i = 0; i < STG - 1; i++) {
        if (i < NC) cp_chunk(i, i * 32);
        CP_COMMIT();
    }

    const int pa_off = (wm * 32 + gid) * 36 + tig;
    const int pb_off = (wn * WN + gid) * 36 + tig;

    for (int i = 0; i < NC; i++) {
        CP_WAIT2();
        __syncthreads();

        const int st = i & (STG - 1);
        const uint32_t* sa = sm + st * CH + pa_off;
        const uint32_t* sb = sm + st * CH + BM * 36 + pb_off;

#pragma unroll
        for (int s = 0; s < 4; s++) {
            const int ko = s * 8;
            uint32_t a[2][4];
#pragma unroll
            for (int f = 0; f < 2; f++) {
                const uint32_t* q = sa + f * (16 * 36) + ko;
                a[f][0] = q[0];
                a[f][1] = q[8 * 36];
                a[f][2] = q[4];
                a[f][3] = q[8 * 36 + 4];
            }
            uint32_t b[NB][2];
#pragma unroll
            for (int nb = 0; nb < NB; nb++) {
                const uint32_t* q = sb + nb * (8 * 36) + ko;
                b[nb][0] = q[0];
                b[nb][1] = q[4];
            }
#pragma unroll
            for (int f = 0; f < 2; f++)
#pragma unroll
                for (int nb = 0; nb < NB; nb++)
                    mma_tf32(d[f][nb], a[f], b[nb]);
        }

        const int nx = i + STG - 1;
        if (nx < NC) cp_chunk(nx & (STG - 1), nx * 32);
        CP_COMMIT();
    }

    // ---- epilogue ----
#pragma unroll
    for (int f = 0; f < 2; f++) {
        int m0 = mbase + wm * 32 + f * 16 + gid;
        int m1 = m0 + 8;
        float* row0;
        float* row1;
        if (OUT_MODE == 0) {
            row0 = C + (size_t)m0 * Nld;
            row1 = C + (size_t)m1 * Nld;
        } else {
            row0 = C + (size_t)((m0 & 63) * BB + (m0 >> 6)) * Nld;
            row1 = C + (size_t)((m1 & 63) * BB + (m1 >> 6)) * Nld;
        }
#pragma unroll
        for (int nb = 0; nb < NB; nb++) {
            int cn = n0 + wn * WN + nb * 8 + 2 * tig;
            float2 bb = make_float2(0.f, 0.f);
            if (bias) bb = *(const float2*)(bias + cn);
            float2 o0 = make_float2(d[f][nb][0] + bb.x, d[f][nb][1] + bb.y);
            float2 o1 = make_float2(d[f][nb][2] + bb.x, d[f][nb][3] + bb.y);
            *(float2*)(row0 + cn) = o0;
            *(float2*)(row1 + cn) = o1;
        }
    }
}

// Fused wq + uh GEMM: grid.y 0..7 -> wq (M=1024), 8..39 -> uh (M=4096); grid.x=8
__global__ __launch_bounds__(256, 2)
void gqc_mma(const float* __restrict__ rsrc, const float* __restrict__ rmem,
             const float* __restrict__ rWq, const float* __restrict__ bq,
             const float* __restrict__ rWc,
             float* __restrict__ wq, float* __restrict__ uh) {
    int my = blockIdx.y;
    if (my < 8)
        mma_gemm_dev<128, 64, 16, 0>(rsrc, rWq, bq, wq, my * 128, blockIdx.x * 64, DD, DD);
    else
        mma_gemm_dev<128, 64, 16, 0>(rmem, rWc, nullptr, uh, (my - 8) * 128, blockIdx.x * 64, DD, DD);
}

// Output GEMM: concat(1024x1024, pre-rounded) @ rWout^T + bias -> (T,B,D)
__global__ __launch_bounds__(256, 2)
void gout_mma(const float* __restrict__ cc, const float* __restrict__ rWout,
              const float* __restrict__ bout, float* __restrict__ out) {
    mma_gemm_dev<64, 64, 32, 1>(cc, rWout, bout, out, blockIdx.y * 64, blockIdx.x * 64,
                                DD, 2 * DD);
}

// ---------------------------------------------------------------------------
// Align + sparsemax (Michelot, 4 rows in parallel via named barriers) +
// context + concat (concat written tf32-pre-rounded).
// ---------------------------------------------------------------------------
__global__ __launch_bounds__(256)
void align4_kernel(const float* __restrict__ wq, const float* __restrict__ uh,
                   const float* __restrict__ mem, const int* __restrict__ mask,
                   const float* __restrict__ v, const float* __restrict__ rsrc,
                   float* __restrict__ out_align, float* __restrict__ concat) {
    __shared__ float s_wq[4][DD];
    __shared__ float s_v[DD];
    __shared__ float s_z[4][SS];
    __shared__ float s_p[4][SS];
    __shared__ int s_mk[SS];
    __shared__ float s_red[4][2][2];   // [tt][warp-in-pair][sum,cnt]

    const int tid = threadIdx.x;
    const int b  = blockIdx.x >> 4;
    const int t0 = (blockIdx.x & 15) * 4;

    for (int i = tid; i < 4 * DD; i += 256) {
        int tt = i >> 9, d = i & 511;
        s_wq[tt][d] = wq[((size_t)(b * TT + t0 + tt)) * DD + d];
    }
    s_v[tid] = v[tid];
    s_v[tid + 256] = v[tid + 256];
    s_mk[tid] = mask[b * SS + tid];
    __syncthreads();

    const int warp = tid >> 5, lane = tid & 31;
    for (int s = warp; s < SS; s += 8) {
        if (!s_mk[s]) {
            if (lane == 0) {
                s_z[0][s] = -1e9f; s_z[1][s] = -1e9f;
                s_z[2][s] = -1e9f; s_z[3][s] = -1e9f;
            }
            continue;
        }
        const float* uhr = uh + ((size_t)(b * SS + s)) * DD;
        float a0 = 0.f, a1 = 0.f, a2 = 0.f, a3 = 0.f;
#pragma unroll
        for (int i = 0; i < 16; i++) {
            int d = lane + i * 32;
            float u = uhr[d];
            float vv = s_v[d];
            a0 = fmaf(vv, htanh(s_wq[0][d] + u), a0);
            a1 = fmaf(vv, htanh(s_wq[1][d] + u), a1);
            a2 = fmaf(vv, htanh(s_wq[2][d] + u), a2);
            a3 = fmaf(vv, htanh(s_wq[3][d] + u), a3);
        }
#pragma unroll
        for (int off = 16; off; off >>= 1) {
            a0 += __shfl_xor_sync(0xffffffffu, a0, off);
            a1 += __shfl_xor_sync(0xffffffffu, a1, off);
            a2 += __shfl_xor_sync(0xffffffffu, a2, off);
            a3 += __shfl_xor_sync(0xffffffffu, a3, off);
        }
        if (lane == 0) {
            s_z[0][s] = a0; s_z[1][s] = a1; s_z[2][s] = a2; s_z[3][s] = a3;
        }
    }
    __syncthreads();

    // ---- sparsemax via Michelot, 4 rows concurrently (64 threads/row) ----
    {
        const int tt = tid >> 6;       // row 0..3
        const int u  = tid & 63;       // thread within row
        const int lw = (tid >> 5) & 1; // warp within pair
        float z[4];
        bool act[4];
#pragma unroll
        for (int j = 0; j < 4; j++) {
            z[j] = s_z[tt][u + 64 * j];
            act[j] = true;
        }
        float tau = 0.0f;
        int prev = -1;
        for (int it = 0; it < 260; it++) {
            float sv = 0.f, cv = 0.f;
#pragma unroll
            for (int j = 0; j < 4; j++)
                if (act[j]) { sv += z[j]; cv += 1.0f; }
#pragma unroll
            for (int off = 16; off; off >>= 1) {
                sv += __shfl_xor_sync(0xffffffffu, sv, off);
                cv += __shfl_xor_sync(0xffffffffu, cv, off);
            }
            if (lane == 0) { s_red[tt][lw][0] = sv; s_red[tt][lw][1] = cv; }
            BAR64(1 + tt);
            float ts = s_red[tt][0][0] + s_red[tt][1][0];
            float tc = s_red[tt][0][1] + s_red[tt][1][1];
            BAR64(1 + tt);              // protect s_red before next write
            int c = (int)tc;
            if (c == prev) break;
            tau = (ts - 1.0f) / tc;
            prev = c;
#pragma unroll
            for (int j = 0; j < 4; j++) act[j] = z[j] > tau;
        }
#pragma unroll
        for (int j = 0; j < 4; j++) {
            float p = fmaxf(z[j] - tau, 0.0f);
            s_p[tt][u + 64 * j] = p;
            out_align[((size_t)(t0 + tt) * BB + b) * SS + u + 64 * j] = p;
        }
    }
    __syncthreads();

    // ---- context vectors (raw mem; result tf32-rounded into concat) ----
    const int d0 = tid, d1 = tid + 256;
    const float* memb = mem + (size_t)b * SS * DD;
    float c00 = 0.f, c01 = 0.f, c10 = 0.f, c11 = 0.f;
    float c20 = 0.f, c21 = 0.f, c30 = 0.f, c31 = 0.f;
    for (int s = 0; s < SS; s++) {
        float p0 = s_p[0][s], p1 = s_p[1][s], p2 = s_p[2][s], p3 = s_p[3][s];
        if (p0 + p1 + p2 + p3 != 0.0f) {
            const float* row = memb + (size_t)s * DD;
            float r0 = row[d0], r1 = row[d1];
            c00 = fmaf(p0, r0, c00); c01 = fmaf(p0, r1, c01);
            c10 = fmaf(p1, r0, c10); c11 = fmaf(p1, r1, c11);
            c20 = fmaf(p2, r0, c20); c21 = fmaf(p2, r1, c21);
            c30 = fmaf(p3, r0, c30); c31 = fmaf(p3, r1, c31);
        }
    }
    float cc0[4] = {c00, c10, c20, c30};
    float cc1[4] = {c01, c11, c21, c31};
#pragma unroll
    for (int tt = 0; tt < 4; tt++) {
        float* crow = concat + (size_t)(b * TT + t0 + tt) * (2 * DD);
        const float* srow = rsrc + (size_t)(b * TT + t0 + tt) * DD;  // already rounded
        crow[d0] = __uint_as_float(to_tf32(cc0[tt]));
        crow[d1] = __uint_as_float(to_tf32(cc1[tt]));
        crow[DD + d0] = srow[d0];
        crow[DD + d1] = srow[d1];
    }
}

// ---------------------------------------------------------------------------
extern "C" void kernel_launch(void* const* d_in, const int* in_sizes, int n_in,
                              void* d_out, int out_size) {
    const float* source      = (const float*)d_in[0];
    const float* memory_bank = (const float*)d_in[1];
    const int*   memory_mask = (const int*)d_in[2];
    const float* W_q         = (const float*)d_in[3];
    const float* b_q         = (const float*)d_in[4];
    const float* W_c         = (const float*)d_in[5];
    const float* v           = (const float*)d_in[6];
    const float* W_out       = (const float*)d_in[7];
    const float* b_out       = (const float*)d_in[8];

    float* out       = (float*)d_out;
    float* out_attn  = out;                         // (T,B,D)
    float* out_align = out + (size_t)TT * BB * DD;  // (T,B,S)

    float *p_wq, *p_uh, *p_cc, *p_rsrc, *p_rmem, *p_rwq, *p_rwc, *p_rwout;
    cudaGetSymbolAddress((void**)&p_wq, g_wq);
    cudaGetSymbolAddress((void**)&p_uh, g_uh);
    cudaGetSymbolAddress((void**)&p_cc, g_concat);
    cudaGetSymbolAddress((void**)&p_rsrc, g_rsrc);
    cudaGetSymbolAddress((void**)&p_rmem, g_rmem);
    cudaGetSymbolAddress((void**)&p_rwq, g_rwq);
    cudaGetSymbolAddress((void**)&p_rwc, g_rwc);
    cudaGetSymbolAddress((void**)&p_rwout, g_rwout);

    const int smem_qc  = 4 * (128 + 64) * 36 * 4;  // 110592
    const int smem_out = 4 * (64 + 64) * 36 * 4;   // 73728
    cudaFuncSetAttribute(gqc_mma, cudaFuncAttributeMaxDynamicSharedMemorySize, smem_qc);
    cudaFuncSetAttribute(gout_mma, cudaFuncAttributeMaxDynamicSharedMemorySize, smem_out);

    // 0) pre-round all GEMM inputs to the tf32 grid (largest segment: 512K f4)
    round_kernel<<<dim3(2048, 5), 256>>>(source, memory_bank, W_q, W_c, W_out,
                                         p_rsrc, p_rmem, p_rwq, p_rwc, p_rwout);

    // 1) wq & uh (tf32 mma.sync + cp.async): 320 CTAs
    gqc_mma<<<dim3(8, 40), 256, smem_qc>>>(
        p_rsrc, p_rmem, p_rwq, b_q, p_rwc, p_wq, p_uh);

    // 2) align + sparsemax + context + concat: 256 CTAs
    align4_kernel<<<BB * (TT / 4), 256>>>(
        p_wq, p_uh, memory_bank, memory_mask, v, p_rsrc, out_align, p_cc);

    // 3) attn_h = concat @ W_out^T + b_out -> (T,B,D): 128 CTAs
    gout_mma<<<dim3(8, 16), 256, smem_out>>>(p_cc, p_rwout, b_out, out_attn);
}